// round 12
// baseline (speedup 1.0000x reference)
#include <cuda_runtime.h>
#include <cuda_fp16.h>
#include <cstdint>

#define DEVFN __device__ __forceinline__

#define NNODES 8192
#define HDIM   128
#define CIN    384
#define KTOT   512
#define FFD    512

// -------- persistent scratch --------
__device__ float  g_w1Tf[HDIM * KTOT];   // f32 [h][k]: k<384 -> h_e part, k>=384 -> h_v part
__device__ __half g_w2T[HDIM * HDIM];
__device__ __half g_w3T[HDIM * HDIM];
__device__ __half g_fwInT[FFD * HDIM];
__device__ __half g_fwOutT[HDIM * FFD];
__device__ float  g_h1[NNODES * HDIM];

// -------- helpers --------
DEVFN uint32_t smaddr(const void* p) { return (uint32_t)__cvta_generic_to_shared(p); }

DEVFN void ldmx4(uint32_t addr, uint32_t& r0, uint32_t& r1, uint32_t& r2, uint32_t& r3) {
    asm volatile("ldmatrix.sync.aligned.m8n8.x4.shared.b16 {%0,%1,%2,%3}, [%4];\n"
                 : "=r"(r0), "=r"(r1), "=r"(r2), "=r"(r3) : "r"(addr));
}

DEVFN void mma16816(float (&c)[4], const uint32_t (&a)[4], uint32_t b0, uint32_t b1) {
    asm volatile(
        "mma.sync.aligned.m16n8k16.row.col.f32.f16.f16.f32 "
        "{%0,%1,%2,%3}, {%4,%5,%6,%7}, {%8,%9}, {%0,%1,%2,%3};\n"
        : "+f"(c[0]), "+f"(c[1]), "+f"(c[2]), "+f"(c[3])
        : "r"(a[0]), "r"(a[1]), "r"(a[2]), "r"(a[3]), "r"(b0), "r"(b1));
}

DEVFN void mma_tf32(float (&c)[4], const uint32_t (&a)[4], uint32_t b0, uint32_t b1) {
    asm volatile(
        "mma.sync.aligned.m16n8k8.row.col.f32.tf32.tf32.f32 "
        "{%0,%1,%2,%3}, {%4,%5,%6,%7}, {%8,%9}, {%0,%1,%2,%3};\n"
        : "+f"(c[0]), "+f"(c[1]), "+f"(c[2]), "+f"(c[3])
        : "r"(a[0]), "r"(a[1]), "r"(a[2]), "r"(a[3]), "r"(b0), "r"(b1));
}

DEVFN float gelu_f(float x) { return 0.5f * x * (1.0f + erff(x * 0.70710678118654752f)); }

// ---- legacy fp16 warp-tile GEMM (A/B stride in halves, k-contiguous) ----
template <int KSTEPS, int MTILES, int PT, int AST, int BST>
DEVFN void gemm_tile(const __half* sAp, const __half* sBp, int rowBase, int colBase,
                     int lane, float (&acc)[MTILES][2 * PT][4]) {
    const int lr = lane & 15;
    const int lc = (lane >> 4) * 8;
#pragma unroll
    for (int ks = 0; ks < KSTEPS; ++ks) {
        const int kk = ks * 16 + lc;
        uint32_t a[MTILES][4];
#pragma unroll
        for (int mt = 0; mt < MTILES; ++mt)
            ldmx4(smaddr(sAp + (size_t)(rowBase + mt * 16 + lr) * AST + kk),
                  a[mt][0], a[mt][1], a[mt][2], a[mt][3]);
#pragma unroll
        for (int p = 0; p < PT; ++p) {
            uint32_t b0, b1, b2, b3;
            ldmx4(smaddr(sBp + (size_t)(colBase + p * 16 + lr) * BST + kk), b0, b1, b2, b3);
#pragma unroll
            for (int mt = 0; mt < MTILES; ++mt) {
                mma16816(acc[mt][2 * p],     a[mt], b0, b2);
                mma16816(acc[mt][2 * p + 1], a[mt], b1, b3);
            }
        }
    }
}

// ---- TF32 warp-tile GEMM: A f32 [rows][68], B f32 [n][68]; warp tile 48x64 ----
// ldmatrix b16-view of 16x8-f32 tiles gives exactly the tf32 m16n8k8 fragments.
template <int KSTEPS>
DEVFN void gemm_tile_tf32(const float* sAp, const float* sBp, int rowBase, int colBase,
                          int lane, float (&acc)[3][8][4]) {
    const int lr = lane & 15;
    const int hc = (lane >> 4) * 16;      // byte offset: colgroup (4 f32)
#pragma unroll
    for (int ks = 0; ks < KSTEPS; ++ks) {
        const int kb = ks * 32;           // byte offset: 8 f32 per K-step
        uint32_t a[3][4];
#pragma unroll
        for (int mt = 0; mt < 3; ++mt)
            ldmx4(smaddr(sAp + (rowBase + mt * 16 + lr) * 68) + kb + hc,
                  a[mt][0], a[mt][1], a[mt][2], a[mt][3]);
#pragma unroll
        for (int p = 0; p < 4; ++p) {
            uint32_t b0, b1, b2, b3;
            ldmx4(smaddr(sBp + (colBase + p * 16 + lr) * 68) + kb + hc, b0, b1, b2, b3);
#pragma unroll
            for (int mt = 0; mt < 3; ++mt) {
                mma_tf32(acc[mt][2 * p],     a[mt], b0, b2);   // n-rows p*16..+7
                mma_tf32(acc[mt][2 * p + 1], a[mt], b1, b3);   // n-rows p*16+8..+15
            }
        }
    }
}

template <int MTILES, int NT, int DST>
DEVFN void epi_gelu_store(float (&acc)[MTILES][NT][4], const float* __restrict__ bias,
                          __half* dst, int rowBase, int colBase, int lane) {
    const int g = lane >> 2, tg = lane & 3;
#pragma unroll
    for (int mt = 0; mt < MTILES; ++mt) {
        const int r0 = rowBase + mt * 16 + g;
#pragma unroll
        for (int nt = 0; nt < NT; ++nt) {
            const int cc = colBase + nt * 8 + tg * 2;
            const float2 b = __ldg((const float2*)(bias + cc));
            float v0 = gelu_f(acc[mt][nt][0] + b.x);
            float v1 = gelu_f(acc[mt][nt][1] + b.y);
            float v2 = gelu_f(acc[mt][nt][2] + b.x);
            float v3 = gelu_f(acc[mt][nt][3] + b.y);
            *(__half2*)(dst + (size_t)r0 * DST + cc)       = __floats2half2_rn(v0, v1);
            *(__half2*)(dst + (size_t)(r0 + 8) * DST + cc) = __floats2half2_rn(v2, v3);
        }
    }
}

// -------- kernel 0: weight transpose/convert --------
__global__ void prep_weights(const float* __restrict__ w1, const float* __restrict__ w2,
                             const float* __restrict__ w3, const float* __restrict__ fwin,
                             const float* __restrict__ fwout) {
    int i = blockIdx.x * 256 + threadIdx.x;
    if (i < 65536) {                       // w1Tf f32 [h][k]
        int h = i >> 9, k = i & 511;
        g_w1Tf[i] = (k < 384) ? w1[(128 + k) * 128 + h] : w1[(k - 384) * 128 + h];
    } else if (i < 81920) {
        int j = i - 65536; int h = j >> 7, k = j & 127;
        g_w2T[j] = __float2half(w2[k * 128 + h]);
    } else if (i < 98304) {
        int j = i - 81920; int h = j >> 7, k = j & 127;
        g_w3T[j] = __float2half(w3[k * 128 + h]);
    } else if (i < 163840) {
        int j = i - 98304; int f = j >> 7, k = j & 127;
        g_fwInT[j] = __float2half(fwin[k * 512 + f]);
    } else if (i < 229376) {
        int j = i - 163840; int h = j >> 9, k = j & 511;
        g_fwOutT[j] = __float2half(fwout[k * 128 + h]);
    }
}

// -------- kernel 1: TF32 GEMM1 + fp16 GEMM2/3 + mask-sum + LN1 --------
// CTA = 4 nodes = 192 h_e rows. 256 threads = 8 warps (4 node-warps x 2 col-halves).
// smem: region0 @0: sA f32 [192][68] (52224) aliased by sM f16 [192][136] (52224)
//       region1 @52224: sB f32 [128][68] (34816) aliased by w2T/w3T f16 [128][136]
//       tails: sHv @87040 (2048), sMask @89088 (768), sDh @89856 (2048) -> 91904
#define K1_SMEM 91904
__global__ void __launch_bounds__(256, 2) k1_msg(
    const float* __restrict__ h_v, const float* __restrict__ h_e,
    const float* __restrict__ mask_attend,
    const float* __restrict__ w1_b, const float* __restrict__ w2_b,
    const float* __restrict__ w3_b,
    const float* __restrict__ ln1_g, const float* __restrict__ ln1_b) {
    extern __shared__ char smem[];
    float*  sAf   = (float*)smem;                     // [192][68] f32 (GEMM1 A)
    __half* sM    = (__half*)smem;                    // [192][136] f16 (after GEMM1)
    float*  sBf   = (float*)(smem + 52224);           // [128][68] f32 (GEMM1 B)
    __half* sB    = (__half*)(smem + 52224);          // [128][136] f16 (GEMM2/3 B)
    float*  sHv   = (float*)(smem + 87040);
    float*  sMask = (float*)(smem + 89088);
    float*  sDh   = (float*)(smem + 89856);

    const int tid = threadIdx.x, lane = tid & 31, wid = tid >> 5;
    const int wm = wid & 3, wn = wid >> 2;
    const int rowBase = wm * 48, colBase = wn * 64;
    const size_t tileRow = (size_t)blockIdx.x * 192;
    const int nodeBase = blockIdx.x * 4;

    for (int i = tid; i < 512; i += 256) sHv[i]   = h_v[(size_t)nodeBase * 128 + i];
    for (int i = tid; i < 192; i += 256) sMask[i] = mask_attend[tileRow + i];
    __syncthreads();

    float acc[3][8][4];
#pragma unroll
    for (int a = 0; a < 3; a++)
#pragma unroll
        for (int b = 0; b < 8; b++)
#pragma unroll
            for (int c = 0; c < 4; c++) acc[a][b][c] = 0.f;

    // ---- GEMM1 (TF32): [192 x 512] x [512 -> 128], K in 8 chunks of 64 ----
    const uint4* heBase = (const uint4*)(h_e + tileRow * CIN);
    for (int kc = 0; kc < 8; ++kc) {
        // stage A: 192 rows x 64 f32, stride 68 (conflict-free for ldmatrix)
#pragma unroll
        for (int i = 0; i < 12; ++i) {
            int idx = tid + i * 256;              // < 3072
            int r = idx >> 4, c4 = idx & 15;
            uint4 v;
            if (kc < 6) v = __ldcs(heBase + (size_t)r * 96 + kc * 16 + c4);
            else        v = *(const uint4*)(sHv + (r / 48) * 128 + (kc - 6) * 64 + c4 * 4);
            *(uint4*)(sAf + r * 68 + c4 * 4) = v;
        }
        // stage B: w1Tf chunk 128 x 64 f32, stride 68
#pragma unroll
        for (int i = 0; i < 8; ++i) {
            int idx = tid + i * 256;              // < 2048
            int n = idx >> 4, c4 = idx & 15;
            *(uint4*)(sBf + n * 68 + c4 * 4) =
                *(const uint4*)(g_w1Tf + n * 512 + kc * 64 + c4 * 4);
        }
        __syncthreads();
        gemm_tile_tf32<8>(sAf, sBf, rowBase, colBase, lane, acc);
        __syncthreads();
    }

    // epilogue 1: +b1, gelu -> sM f16 (overwrites dead sA); then stage w2T
    epi_gelu_store<3, 8, 136>(acc, w1_b, sM, rowBase, colBase, lane);
    __syncthreads();
#pragma unroll
    for (int i = 0; i < 8; ++i) {
        int idx = tid + i * 256;
        int n = idx >> 4, j = idx & 15;
        *(uint4*)(sB + n * 136 + j * 8) = *(const uint4*)(g_w2T + n * 128 + j * 8);
    }
    __syncthreads();

    // ---- GEMM2 (fp16): [192 x 128] x [128 -> 128] ----
#pragma unroll
    for (int a = 0; a < 3; a++)
#pragma unroll
        for (int b = 0; b < 8; b++)
#pragma unroll
            for (int c = 0; c < 4; c++) acc[a][b][c] = 0.f;
    gemm_tile<8, 3, 4, 136, 136>(sM, sB, rowBase, colBase, lane, acc);
    __syncthreads();

    epi_gelu_store<3, 8, 136>(acc, w2_b, sM, rowBase, colBase, lane);
#pragma unroll
    for (int i = 0; i < 8; ++i) {
        int idx = tid + i * 256;
        int n = idx >> 4, j = idx & 15;
        *(uint4*)(sB + n * 136 + j * 8) = *(const uint4*)(g_w3T + n * 128 + j * 8);
    }
    __syncthreads();

    // ---- GEMM3 (fp16) ----
#pragma unroll
    for (int a = 0; a < 3; a++)
#pragma unroll
        for (int b = 0; b < 8; b++)
#pragma unroll
            for (int c = 0; c < 4; c++) acc[a][b][c] = 0.f;
    gemm_tile<8, 3, 4, 136, 136>(sM, sB, rowBase, colBase, lane, acc);

    // epilogue 3: +b3, * mask_attend, warp-local sum over the node's 48 rows
    {
        const int g = lane >> 2, tg = lane & 3;
        float mk0[3], mk1[3];
#pragma unroll
        for (int mt = 0; mt < 3; ++mt) {
            mk0[mt] = sMask[rowBase + mt * 16 + g];
            mk1[mt] = sMask[rowBase + mt * 16 + 8 + g];
        }
#pragma unroll
        for (int nt = 0; nt < 8; ++nt) {
            const int cc = colBase + nt * 8 + tg * 2;
            const float2 b3 = __ldg((const float2*)(w3_b + cc));
            float s0 = 0.f, s1 = 0.f;
#pragma unroll
            for (int mt = 0; mt < 3; ++mt) {
                s0 += (acc[mt][nt][0] + b3.x) * mk0[mt] + (acc[mt][nt][2] + b3.x) * mk1[mt];
                s1 += (acc[mt][nt][1] + b3.y) * mk0[mt] + (acc[mt][nt][3] + b3.y) * mk1[mt];
            }
#pragma unroll
            for (int o = 4; o <= 16; o <<= 1) {
                s0 += __shfl_xor_sync(0xffffffffu, s0, o);
                s1 += __shfl_xor_sync(0xffffffffu, s1, o);
            }
            if (g == 0) *(float2*)(sDh + wm * 128 + cc) = make_float2(s0, s1);
        }
    }
    __syncthreads();

    // LN1: warps 0..3, one node each
    if (wid < 4) {
        const int node = wid;
        float x[4], sum = 0.f;
#pragma unroll
        for (int j = 0; j < 4; ++j) {
            int c = lane + 32 * j;
            x[j] = sHv[node * 128 + c] + sDh[node * 128 + c] * (1.0f / 30.0f);
            sum += x[j];
        }
#pragma unroll
        for (int o = 16; o >= 1; o >>= 1) sum += __shfl_xor_sync(0xffffffffu, sum, o);
        float mu = sum * (1.0f / 128.0f);
        float vs = 0.f;
#pragma unroll
        for (int j = 0; j < 4; ++j) { float d = x[j] - mu; vs += d * d; }
#pragma unroll
        for (int o = 16; o >= 1; o >>= 1) vs += __shfl_xor_sync(0xffffffffu, vs, o);
        float rs = rsqrtf(vs * (1.0f / 128.0f) + 1e-5f);
#pragma unroll
        for (int j = 0; j < 4; ++j) {
            int c = lane + 32 * j;
            g_h1[(size_t)(nodeBase + node) * 128 + c] =
                (x[j] - mu) * rs * __ldg(ln1_g + c) + __ldg(ln1_b + c);
        }
    }
}

// -------- kernel 2: FFN + residual + LN2 + mask_v --------
#define K2_SW 0
#define K2_SF 139264
#define K2_SH 155904
#define K2_SX 160256
#define K2_SMEM 168704
__global__ void __launch_bounds__(256) k2_ffn(
    const float* __restrict__ mask_v,
    const float* __restrict__ fw_in_b, const float* __restrict__ fw_out_b,
    const float* __restrict__ ln2_g, const float* __restrict__ ln2_b,
    float* __restrict__ out) {
    extern __shared__ char smem[];
    __half* sW = (__half*)(smem + K2_SW);
    __half* sF = (__half*)(smem + K2_SF);
    __half* sH = (__half*)(smem + K2_SH);
    float*  sX = (float*)(smem + K2_SX);

    const int tid = threadIdx.x, lane = tid & 31, wid = tid >> 5;
    const int node0 = blockIdx.x * 16;

    for (int i = tid; i < 2048; i += 256) {
        int r = i >> 7, c = i & 127;
        sH[r * 136 + c] = __float2half(g_h1[(size_t)(node0 + r) * 128 + c]);
    }
    for (int i = tid; i < 8192; i += 256) {
        int n = i >> 4, j = i & 15;
        *(uint4*)(sW + n * 136 + j * 8) = *(const uint4*)(g_fwInT + n * 128 + j * 8);
    }
    __syncthreads();
    {
        float acc[1][8][4];
#pragma unroll
        for (int b = 0; b < 8; b++)
#pragma unroll
            for (int c = 0; c < 4; c++) acc[0][b][c] = 0.f;
        gemm_tile<8, 1, 4, 136, 136>(sH, sW, 0, wid * 64, lane, acc);
        __syncthreads();
        epi_gelu_store<1, 8, 520>(acc, fw_in_b, sF, 0, wid * 64, lane);
    }
    for (int i = tid; i < 8192; i += 256) {
        int n = i >> 6, j = i & 63;
        *(uint4*)(sW + n * 520 + j * 8) = *(const uint4*)(g_fwOutT + n * 512 + j * 8);
    }
    __syncthreads();
    {
        float acc[1][2][4];
#pragma unroll
        for (int b = 0; b < 2; b++)
#pragma unroll
            for (int c = 0; c < 4; c++) acc[0][b][c] = 0.f;
        gemm_tile<32, 1, 1, 520, 520>(sF, sW, 0, wid * 16, lane, acc);
        const int g = lane >> 2, tg = lane & 3;
#pragma unroll
        for (int nt = 0; nt < 2; ++nt) {
            const int cc = wid * 16 + nt * 8 + tg * 2;
            const float2 b = __ldg((const float2*)(fw_out_b + cc));
            const float2 r0 = *(const float2*)(g_h1 + (size_t)(node0 + g) * 128 + cc);
            const float2 r1 = *(const float2*)(g_h1 + (size_t)(node0 + 8 + g) * 128 + cc);
            sX[g * 132 + cc]           = acc[0][nt][0] + b.x + r0.x;
            sX[g * 132 + cc + 1]       = acc[0][nt][1] + b.y + r0.y;
            sX[(g + 8) * 132 + cc]     = acc[0][nt][2] + b.x + r1.x;
            sX[(g + 8) * 132 + cc + 1] = acc[0][nt][3] + b.y + r1.y;
        }
    }
    __syncthreads();
#pragma unroll
    for (int rr = 0; rr < 2; ++rr) {
        const int r = wid * 2 + rr;
        float x[4], sum = 0.f;
#pragma unroll
        for (int j = 0; j < 4; ++j) { x[j] = sX[r * 132 + lane + 32 * j]; sum += x[j]; }
#pragma unroll
        for (int o = 16; o >= 1; o >>= 1) sum += __shfl_xor_sync(0xffffffffu, sum, o);
        float mu = sum * (1.0f / 128.0f);
        float vs = 0.f;
#pragma unroll
        for (int j = 0; j < 4; ++j) { float d = x[j] - mu; vs += d * d; }
#pragma unroll
        for (int o = 16; o >= 1; o >>= 1) vs += __shfl_xor_sync(0xffffffffu, vs, o);
        float rs = rsqrtf(vs * (1.0f / 128.0f) + 1e-5f);
        float mv = mask_v[node0 + r];
#pragma unroll
        for (int j = 0; j < 4; ++j) {
            int c = lane + 32 * j;
            out[(size_t)(node0 + r) * 128 + c] =
                ((x[j] - mu) * rs * __ldg(ln2_g + c) + __ldg(ln2_b + c)) * mv;
        }
    }
}

// -------- launcher --------
extern "C" void kernel_launch(void* const* d_in, const int* in_sizes, int n_in,
                              void* d_out, int out_size) {
    const float* h_v         = (const float*)d_in[0];
    const float* h_e         = (const float*)d_in[1];
    const float* mask_v      = (const float*)d_in[2];
    const float* mask_attend = (const float*)d_in[3];
    const float* w1_b        = (const float*)d_in[5];
    const float* w2_b        = (const float*)d_in[7];
    const float* w3_b        = (const float*)d_in[9];
    const float* ln1_g       = (const float*)d_in[10];
    const float* ln1_b       = (const float*)d_in[11];
    const float* ln2_g       = (const float*)d_in[12];
    const float* ln2_b       = (const float*)d_in[13];
    const float* fw_in_b     = (const float*)d_in[15];
    const float* fw_out_b    = (const float*)d_in[17];
    float* out = (float*)d_out;

    static bool attr_done = false;
    if (!attr_done) {
        cudaFuncSetAttribute(k1_msg, cudaFuncAttributeMaxDynamicSharedMemorySize, K1_SMEM);
        cudaFuncSetAttribute(k2_ffn, cudaFuncAttributeMaxDynamicSharedMemorySize, K2_SMEM);
        attr_done = true;
    }

    prep_weights<<<896, 256>>>((const float*)d_in[4], (const float*)d_in[6],
                               (const float*)d_in[8], (const float*)d_in[14],
                               (const float*)d_in[16]);
    k1_msg<<<NNODES / 4, 256, K1_SMEM>>>(h_v, h_e, mask_attend,
                                         w1_b, w2_b, w3_b, ln1_g, ln1_b);
    k2_ffn<<<NNODES / 16, 256, K2_SMEM>>>(mask_v, fw_in_b, fw_out_b,
                                          ln2_g, ln2_b, out);
}

// round 13
// speedup vs baseline: 1.3082x; 1.3082x over previous
#include <cuda_runtime.h>
#include <cuda_fp16.h>
#include <cstdint>

#define DEVFN __device__ __forceinline__

#define NNODES 8192
#define HDIM   128
#define CIN    384
#define KTOT   512
#define FFD    512

// -------- persistent scratch --------
__device__ __half g_w1T[HDIM * KTOT];    // [h][k]: k<384 -> h_e part, k>=384 -> h_v part
__device__ __half g_w2T[HDIM * HDIM];
__device__ __half g_w3T[HDIM * HDIM];
__device__ __half g_fwInT[FFD * HDIM];
__device__ __half g_fwOutT[HDIM * FFD];
__device__ float  g_h1[NNODES * HDIM];

// -------- helpers --------
DEVFN uint32_t smaddr(const void* p) { return (uint32_t)__cvta_generic_to_shared(p); }

DEVFN void ldmx4(uint32_t addr, uint32_t& r0, uint32_t& r1, uint32_t& r2, uint32_t& r3) {
    asm volatile("ldmatrix.sync.aligned.m8n8.x4.shared.b16 {%0,%1,%2,%3}, [%4];\n"
                 : "=r"(r0), "=r"(r1), "=r"(r2), "=r"(r3) : "r"(addr));
}

DEVFN void mma16816(float (&c)[4], const uint32_t (&a)[4], uint32_t b0, uint32_t b1) {
    asm volatile(
        "mma.sync.aligned.m16n8k16.row.col.f32.f16.f16.f32 "
        "{%0,%1,%2,%3}, {%4,%5,%6,%7}, {%8,%9}, {%0,%1,%2,%3};\n"
        : "+f"(c[0]), "+f"(c[1]), "+f"(c[2]), "+f"(c[3])
        : "r"(a[0]), "r"(a[1]), "r"(a[2]), "r"(a[3]), "r"(b0), "r"(b1));
}

DEVFN float gelu_f(float x) { return 0.5f * x * (1.0f + erff(x * 0.70710678118654752f)); }

// fp16 warp-tile GEMM (A/B k-contiguous, strides in halves)
template <int KSTEPS, int MTILES, int PT, int AST, int BST>
DEVFN void gemm_tile(const __half* sAp, const __half* sBp, int rowBase, int colBase,
                     int lane, float (&acc)[MTILES][2 * PT][4]) {
    const int lr = lane & 15;
    const int lc = (lane >> 4) * 8;
#pragma unroll
    for (int ks = 0; ks < KSTEPS; ++ks) {
        const int kk = ks * 16 + lc;
        uint32_t a[MTILES][4];
#pragma unroll
        for (int mt = 0; mt < MTILES; ++mt)
            ldmx4(smaddr(sAp + (size_t)(rowBase + mt * 16 + lr) * AST + kk),
                  a[mt][0], a[mt][1], a[mt][2], a[mt][3]);
#pragma unroll
        for (int p = 0; p < PT; ++p) {
            uint32_t b0, b1, b2, b3;
            ldmx4(smaddr(sBp + (size_t)(colBase + p * 16 + lr) * BST + kk), b0, b1, b2, b3);
#pragma unroll
            for (int mt = 0; mt < MTILES; ++mt) {
                mma16816(acc[mt][2 * p],     a[mt], b0, b2);
                mma16816(acc[mt][2 * p + 1], a[mt], b1, b3);
            }
        }
    }
}

template <int MTILES, int NT, int DST>
DEVFN void epi_gelu_store(float (&acc)[MTILES][NT][4], const float* __restrict__ bias,
                          __half* dst, int rowBase, int colBase, int lane) {
    const int g = lane >> 2, tg = lane & 3;
#pragma unroll
    for (int mt = 0; mt < MTILES; ++mt) {
        const int r0 = rowBase + mt * 16 + g;
#pragma unroll
        for (int nt = 0; nt < NT; ++nt) {
            const int cc = colBase + nt * 8 + tg * 2;
            const float2 b = __ldg((const float2*)(bias + cc));
            float v0 = gelu_f(acc[mt][nt][0] + b.x);
            float v1 = gelu_f(acc[mt][nt][1] + b.y);
            float v2 = gelu_f(acc[mt][nt][2] + b.x);
            float v3 = gelu_f(acc[mt][nt][3] + b.y);
            *(__half2*)(dst + (size_t)r0 * DST + cc)       = __floats2half2_rn(v0, v1);
            *(__half2*)(dst + (size_t)(r0 + 8) * DST + cc) = __floats2half2_rn(v2, v3);
        }
    }
}

// -------- kernel 0: weight transpose/convert to fp16 --------
__global__ void prep_weights(const float* __restrict__ w1, const float* __restrict__ w2,
                             const float* __restrict__ w3, const float* __restrict__ fwin,
                             const float* __restrict__ fwout) {
    int i = blockIdx.x * 256 + threadIdx.x;
    if (i < 65536) {
        int h = i >> 9, k = i & 511;
        float v = (k < 384) ? w1[(128 + k) * 128 + h] : w1[(k - 384) * 128 + h];
        g_w1T[i] = __float2half(v);
    } else if (i < 81920) {
        int j = i - 65536; int h = j >> 7, k = j & 127;
        g_w2T[j] = __float2half(w2[k * 128 + h]);
    } else if (i < 98304) {
        int j = i - 81920; int h = j >> 7, k = j & 127;
        g_w3T[j] = __float2half(w3[k * 128 + h]);
    } else if (i < 163840) {
        int j = i - 98304; int f = j >> 7, k = j & 127;
        g_fwInT[j] = __float2half(fwin[k * 512 + f]);
    } else if (i < 229376) {
        int j = i - 163840; int h = j >> 9, k = j & 511;
        g_fwOutT[j] = __float2half(fwout[k * 128 + h]);
    }
}

// -------- kernel 1: msg MLP (GEMM1 double-buffered) + mask-sum + LN1 --------
// CTA = 4 nodes = 192 h_e rows. 256 threads = 8 warps (4 node x 2 col-halves).
// smem layout:
//   @0      bufA[2]: 2 x [192][72] f16 (2 x 27648 = 55296); sM [192][136] (52224) aliases
//   @55296  bufB[2]: 2 x [128][72] f16 (2 x 18432 = 36864); sB [128][136] (34816) aliases
//   @92160  sHv 512 f32 (2048)
//   @94208  sMask 192 f32 (768)
//   @94976  sDh 512 f32 (2048)   -> total 97024 (2 CTAs/SM)
#define A_BUF   27648
#define B_BASE  55296
#define B_BUF   18432
#define K1_SMEM 97024
__global__ void __launch_bounds__(256, 2) k1_msg(
    const float* __restrict__ h_v, const float* __restrict__ h_e,
    const float* __restrict__ mask_attend,
    const float* __restrict__ w1_b, const float* __restrict__ w2_b,
    const float* __restrict__ w3_b,
    const float* __restrict__ ln1_g, const float* __restrict__ ln1_b) {
    extern __shared__ char smem[];
    __half* sA0   = (__half*)smem;                    // bufA base
    __half* sM    = (__half*)smem;                    // [192][136], post-GEMM1
    __half* sB0   = (__half*)(smem + B_BASE);         // bufB base
    __half* sB    = (__half*)(smem + B_BASE);         // [128][136], GEMM2/3
    float*  sHv   = (float*)(smem + 92160);
    float*  sMask = (float*)(smem + 94208);
    float*  sDh   = (float*)(smem + 94976);

    const int tid = threadIdx.x, lane = tid & 31, wid = tid >> 5;
    const int wm = wid & 3, wn = wid >> 2;
    const int rowBase = wm * 48, colBase = wn * 64;
    const size_t tileRow = (size_t)blockIdx.x * 192;
    const int nodeBase = blockIdx.x * 4;

    for (int i = tid; i < 512; i += 256) sHv[i]   = h_v[(size_t)nodeBase * 128 + i];
    for (int i = tid; i < 192; i += 256) sMask[i] = mask_attend[tileRow + i];
    __syncthreads();

    const float4* heBase = (const float4*)(h_e + tileRow * CIN);

    // staging lambdas (chunk kc -> buffer bf)
    auto stageA = [&](int kc, int bf) {
#pragma unroll
        for (int i = 0; i < 12; ++i) {
            int idx = tid + i * 256;              // < 3072
            int r = idx >> 4, c4 = idx & 15;
            float4 v;
            if (kc < 6) v = __ldcs(heBase + (size_t)r * 96 + kc * 16 + c4);
            else        v = *(const float4*)(sHv + (r / 48) * 128 + (kc - 6) * 64 + c4 * 4);
            __half2* p = (__half2*)(sA0 + bf * (A_BUF / 2) + r * 72 + c4 * 4);
            p[0] = __floats2half2_rn(v.x, v.y);
            p[1] = __floats2half2_rn(v.z, v.w);
        }
    };
    auto stageB = [&](int kc, int bf) {
#pragma unroll
        for (int i = 0; i < 4; ++i) {
            int idx = tid + i * 256;              // < 1024
            int n = idx >> 3, j = idx & 7;
            *(uint4*)(sB0 + bf * (B_BUF / 2) + n * 72 + j * 8) =
                *(const uint4*)(g_w1T + n * 512 + kc * 64 + j * 8);
        }
    };

    float acc[3][8][4];
#pragma unroll
    for (int a = 0; a < 3; a++)
#pragma unroll
        for (int b = 0; b < 8; b++)
#pragma unroll
            for (int c = 0; c < 4; c++) acc[a][b][c] = 0.f;

    // ---- GEMM1: [192 x 512] x [512 -> 128], 8 K-chunks of 64, double-buffered ----
    stageA(0, 0); stageB(0, 0);
    __syncthreads();
    for (int kc = 0; kc < 8; ++kc) {
        const int cur = kc & 1, nxt = cur ^ 1;
        if (kc < 7) { stageA(kc + 1, nxt); stageB(kc + 1, nxt); }  // overlaps mma below
        gemm_tile<4, 3, 4, 72, 72>(sA0 + cur * (A_BUF / 2), sB0 + cur * (B_BUF / 2),
                                   rowBase, colBase, lane, acc);
        __syncthreads();
    }

    // epilogue 1: +b1, gelu -> sM (aliases bufA); stage w2T -> sB (aliases bufB)
    epi_gelu_store<3, 8, 136>(acc, w1_b, sM, rowBase, colBase, lane);
#pragma unroll
    for (int i = 0; i < 8; ++i) {
        int idx = tid + i * 256;
        int n = idx >> 4, j = idx & 15;
        *(uint4*)(sB + n * 136 + j * 8) = *(const uint4*)(g_w2T + n * 128 + j * 8);
    }
    __syncthreads();

    // ---- GEMM2: [192 x 128] x [128 -> 128] ----
#pragma unroll
    for (int a = 0; a < 3; a++)
#pragma unroll
        for (int b = 0; b < 8; b++)
#pragma unroll
            for (int c = 0; c < 4; c++) acc[a][b][c] = 0.f;
    gemm_tile<8, 3, 4, 136, 136>(sM, sB, rowBase, colBase, lane, acc);
    __syncthreads();

    epi_gelu_store<3, 8, 136>(acc, w2_b, sM, rowBase, colBase, lane);
#pragma unroll
    for (int i = 0; i < 8; ++i) {
        int idx = tid + i * 256;
        int n = idx >> 4, j = idx & 15;
        *(uint4*)(sB + n * 136 + j * 8) = *(const uint4*)(g_w3T + n * 128 + j * 8);
    }
    __syncthreads();

    // ---- GEMM3 ----
#pragma unroll
    for (int a = 0; a < 3; a++)
#pragma unroll
        for (int b = 0; b < 8; b++)
#pragma unroll
            for (int c = 0; c < 4; c++) acc[a][b][c] = 0.f;
    gemm_tile<8, 3, 4, 136, 136>(sM, sB, rowBase, colBase, lane, acc);

    // epilogue 3: +b3, * mask_attend, warp-local sum over the node's 48 rows
    {
        const int g = lane >> 2, tg = lane & 3;
        float mk0[3], mk1[3];
#pragma unroll
        for (int mt = 0; mt < 3; ++mt) {
            mk0[mt] = sMask[rowBase + mt * 16 + g];
            mk1[mt] = sMask[rowBase + mt * 16 + 8 + g];
        }
#pragma unroll
        for (int nt = 0; nt < 8; ++nt) {
            const int cc = colBase + nt * 8 + tg * 2;
            const float2 b3 = __ldg((const float2*)(w3_b + cc));
            float s0 = 0.f, s1 = 0.f;
#pragma unroll
            for (int mt = 0; mt < 3; ++mt) {
                s0 += (acc[mt][nt][0] + b3.x) * mk0[mt] + (acc[mt][nt][2] + b3.x) * mk1[mt];
                s1 += (acc[mt][nt][1] + b3.y) * mk0[mt] + (acc[mt][nt][3] + b3.y) * mk1[mt];
            }
#pragma unroll
            for (int o = 4; o <= 16; o <<= 1) {
                s0 += __shfl_xor_sync(0xffffffffu, s0, o);
                s1 += __shfl_xor_sync(0xffffffffu, s1, o);
            }
            if (g == 0) *(float2*)(sDh + wm * 128 + cc) = make_float2(s0, s1);
        }
    }
    __syncthreads();

    // LN1: warps 0..3, one node each
    if (wid < 4) {
        const int node = wid;
        float x[4], sum = 0.f;
#pragma unroll
        for (int j = 0; j < 4; ++j) {
            int c = lane + 32 * j;
            x[j] = sHv[node * 128 + c] + sDh[node * 128 + c] * (1.0f / 30.0f);
            sum += x[j];
        }
#pragma unroll
        for (int o = 16; o >= 1; o >>= 1) sum += __shfl_xor_sync(0xffffffffu, sum, o);
        float mu = sum * (1.0f / 128.0f);
        float vs = 0.f;
#pragma unroll
        for (int j = 0; j < 4; ++j) { float d = x[j] - mu; vs += d * d; }
#pragma unroll
        for (int o = 16; o >= 1; o >>= 1) vs += __shfl_xor_sync(0xffffffffu, vs, o);
        float rs = rsqrtf(vs * (1.0f / 128.0f) + 1e-5f);
#pragma unroll
        for (int j = 0; j < 4; ++j) {
            int c = lane + 32 * j;
            g_h1[(size_t)(nodeBase + node) * 128 + c] =
                (x[j] - mu) * rs * __ldg(ln1_g + c) + __ldg(ln1_b + c);
        }
    }
}

// -------- kernel 2: FFN + residual + LN2 + mask_v (proven, unchanged) --------
#define K2_SW 0
#define K2_SF 139264
#define K2_SH 155904
#define K2_SX 160256
#define K2_SMEM 168704
__global__ void __launch_bounds__(256) k2_ffn(
    const float* __restrict__ mask_v,
    const float* __restrict__ fw_in_b, const float* __restrict__ fw_out_b,
    const float* __restrict__ ln2_g, const float* __restrict__ ln2_b,
    float* __restrict__ out) {
    extern __shared__ char smem[];
    __half* sW = (__half*)(smem + K2_SW);
    __half* sF = (__half*)(smem + K2_SF);
    __half* sH = (__half*)(smem + K2_SH);
    float*  sX = (float*)(smem + K2_SX);

    const int tid = threadIdx.x, lane = tid & 31, wid = tid >> 5;
    const int node0 = blockIdx.x * 16;

    for (int i = tid; i < 2048; i += 256) {
        int r = i >> 7, c = i & 127;
        sH[r * 136 + c] = __float2half(g_h1[(size_t)(node0 + r) * 128 + c]);
    }
    for (int i = tid; i < 8192; i += 256) {
        int n = i >> 4, j = i & 15;
        *(uint4*)(sW + n * 136 + j * 8) = *(const uint4*)(g_fwInT + n * 128 + j * 8);
    }
    __syncthreads();
    {
        float acc[1][8][4];
#pragma unroll
        for (int b = 0; b < 8; b++)
#pragma unroll
            for (int c = 0; c < 4; c++) acc[0][b][c] = 0.f;
        gemm_tile<8, 1, 4, 136, 136>(sH, sW, 0, wid * 64, lane, acc);
        __syncthreads();
        epi_gelu_store<1, 8, 520>(acc, fw_in_b, sF, 0, wid * 64, lane);
    }
    for (int i = tid; i < 8192; i += 256) {
        int n = i >> 6, j = i & 63;
        *(uint4*)(sW + n * 520 + j * 8) = *(const uint4*)(g_fwOutT + n * 512 + j * 8);
    }
    __syncthreads();
    {
        float acc[1][2][4];
#pragma unroll
        for (int b = 0; b < 2; b++)
#pragma unroll
            for (int c = 0; c < 4; c++) acc[0][b][c] = 0.f;
        gemm_tile<32, 1, 1, 520, 520>(sF, sW, 0, wid * 16, lane, acc);
        const int g = lane >> 2, tg = lane & 3;
#pragma unroll
        for (int nt = 0; nt < 2; ++nt) {
            const int cc = wid * 16 + nt * 8 + tg * 2;
            const float2 b = __ldg((const float2*)(fw_out_b + cc));
            const float2 r0 = *(const float2*)(g_h1 + (size_t)(node0 + g) * 128 + cc);
            const float2 r1 = *(const float2*)(g_h1 + (size_t)(node0 + 8 + g) * 128 + cc);
            sX[g * 132 + cc]           = acc[0][nt][0] + b.x + r0.x;
            sX[g * 132 + cc + 1]       = acc[0][nt][1] + b.y + r0.y;
            sX[(g + 8) * 132 + cc]     = acc[0][nt][2] + b.x + r1.x;
            sX[(g + 8) * 132 + cc + 1] = acc[0][nt][3] + b.y + r1.y;
        }
    }
    __syncthreads();
#pragma unroll
    for (int rr = 0; rr < 2; ++rr) {
        const int r = wid * 2 + rr;
        float x[4], sum = 0.f;
#pragma unroll
        for (int j = 0; j < 4; ++j) { x[j] = sX[r * 132 + lane + 32 * j]; sum += x[j]; }
#pragma unroll
        for (int o = 16; o >= 1; o >>= 1) sum += __shfl_xor_sync(0xffffffffu, sum, o);
        float mu = sum * (1.0f / 128.0f);
        float vs = 0.f;
#pragma unroll
        for (int j = 0; j < 4; ++j) { float d = x[j] - mu; vs += d * d; }
#pragma unroll
        for (int o = 16; o >= 1; o >>= 1) vs += __shfl_xor_sync(0xffffffffu, vs, o);
        float rs = rsqrtf(vs * (1.0f / 128.0f) + 1e-5f);
        float mv = mask_v[node0 + r];
#pragma unroll
        for (int j = 0; j < 4; ++j) {
            int c = lane + 32 * j;
            out[(size_t)(node0 + r) * 128 + c] =
                ((x[j] - mu) * rs * __ldg(ln2_g + c) + __ldg(ln2_b + c)) * mv;
        }
    }
}

// -------- launcher --------
extern "C" void kernel_launch(void* const* d_in, const int* in_sizes, int n_in,
                              void* d_out, int out_size) {
    const float* h_v         = (const float*)d_in[0];
    const float* h_e         = (const float*)d_in[1];
    const float* mask_v      = (const float*)d_in[2];
    const float* mask_attend = (const float*)d_in[3];
    const float* w1_b        = (const float*)d_in[5];
    const float* w2_b        = (const float*)d_in[7];
    const float* w3_b        = (const float*)d_in[9];
    const float* ln1_g       = (const float*)d_in[10];
    const float* ln1_b       = (const float*)d_in[11];
    const float* ln2_g       = (const float*)d_in[12];
    const float* ln2_b       = (const float*)d_in[13];
    const float* fw_in_b     = (const float*)d_in[15];
    const float* fw_out_b    = (const float*)d_in[17];
    float* out = (float*)d_out;

    static bool attr_done = false;
    if (!attr_done) {
        cudaFuncSetAttribute(k1_msg, cudaFuncAttributeMaxDynamicSharedMemorySize, K1_SMEM);
        cudaFuncSetAttribute(k2_ffn, cudaFuncAttributeMaxDynamicSharedMemorySize, K2_SMEM);
        attr_done = true;
    }

    prep_weights<<<896, 256>>>((const float*)d_in[4], (const float*)d_in[6],
                               (const float*)d_in[8], (const float*)d_in[14],
                               (const float*)d_in[16]);
    k1_msg<<<NNODES / 4, 256, K1_SMEM>>>(h_v, h_e, mask_attend,
                                         w1_b, w2_b, w3_b, ln1_g, ln1_b);
    k2_ffn<<<NNODES / 16, 256, K2_SMEM>>>(mask_v, fw_in_b, fw_out_b,
                                          ln2_g, ln2_b, out);
}

// round 14
// speedup vs baseline: 1.5499x; 1.1847x over previous
#include <cuda_runtime.h>
#include <cuda_fp16.h>
#include <cstdint>

#define DEVFN __device__ __forceinline__

#define NNODES 8192
#define HDIM   128
#define CIN    384
#define KTOT   512
#define FFD    512

// -------- persistent scratch --------
__device__ __half g_w1T[HDIM * KTOT];    // [h][k]: k<384 -> h_e part, k>=384 -> h_v part
__device__ __half g_w2T[HDIM * HDIM];
__device__ __half g_w3T[HDIM * HDIM];
__device__ __half g_fwInT[FFD * HDIM];
__device__ __half g_fwOutT[HDIM * FFD];
__device__ float  g_h1[NNODES * HDIM];

// -------- helpers --------
DEVFN uint32_t smaddr(const void* p) { return (uint32_t)__cvta_generic_to_shared(p); }

DEVFN void ldmx4(uint32_t addr, uint32_t& r0, uint32_t& r1, uint32_t& r2, uint32_t& r3) {
    asm volatile("ldmatrix.sync.aligned.m8n8.x4.shared.b16 {%0,%1,%2,%3}, [%4];\n"
                 : "=r"(r0), "=r"(r1), "=r"(r2), "=r"(r3) : "r"(addr));
}

DEVFN void mma16816(float (&c)[4], const uint32_t (&a)[4], uint32_t b0, uint32_t b1) {
    asm volatile(
        "mma.sync.aligned.m16n8k16.row.col.f32.f16.f16.f32 "
        "{%0,%1,%2,%3}, {%4,%5,%6,%7}, {%8,%9}, {%0,%1,%2,%3};\n"
        : "+f"(c[0]), "+f"(c[1]), "+f"(c[2]), "+f"(c[3])
        : "r"(a[0]), "r"(a[1]), "r"(a[2]), "r"(a[3]), "r"(b0), "r"(b1));
}

DEVFN float gelu_f(float x) { return 0.5f * x * (1.0f + erff(x * 0.70710678118654752f)); }

// fp16 warp-tile GEMM (A/B k-contiguous, strides in halves)
template <int KSTEPS, int MTILES, int PT, int AST, int BST>
DEVFN void gemm_tile(const __half* sAp, const __half* sBp, int rowBase, int colBase,
                     int lane, float (&acc)[MTILES][2 * PT][4]) {
    const int lr = lane & 15;
    const int lc = (lane >> 4) * 8;
#pragma unroll
    for (int ks = 0; ks < KSTEPS; ++ks) {
        const int kk = ks * 16 + lc;
        uint32_t a[MTILES][4];
#pragma unroll
        for (int mt = 0; mt < MTILES; ++mt)
            ldmx4(smaddr(sAp + (size_t)(rowBase + mt * 16 + lr) * AST + kk),
                  a[mt][0], a[mt][1], a[mt][2], a[mt][3]);
#pragma unroll
        for (int p = 0; p < PT; ++p) {
            uint32_t b0, b1, b2, b3;
            ldmx4(smaddr(sBp + (size_t)(colBase + p * 16 + lr) * BST + kk), b0, b1, b2, b3);
#pragma unroll
            for (int mt = 0; mt < MTILES; ++mt) {
                mma16816(acc[mt][2 * p],     a[mt], b0, b2);
                mma16816(acc[mt][2 * p + 1], a[mt], b1, b3);
            }
        }
    }
}

template <int MTILES, int NT, int DST>
DEVFN void epi_gelu_store(float (&acc)[MTILES][NT][4], const float* __restrict__ bias,
                          __half* dst, int rowBase, int colBase, int lane) {
    const int g = lane >> 2, tg = lane & 3;
#pragma unroll
    for (int mt = 0; mt < MTILES; ++mt) {
        const int r0 = rowBase + mt * 16 + g;
#pragma unroll
        for (int nt = 0; nt < NT; ++nt) {
            const int cc = colBase + nt * 8 + tg * 2;
            const float2 b = __ldg((const float2*)(bias + cc));
            float v0 = gelu_f(acc[mt][nt][0] + b.x);
            float v1 = gelu_f(acc[mt][nt][1] + b.y);
            float v2 = gelu_f(acc[mt][nt][2] + b.x);
            float v3 = gelu_f(acc[mt][nt][3] + b.y);
            *(__half2*)(dst + (size_t)r0 * DST + cc)       = __floats2half2_rn(v0, v1);
            *(__half2*)(dst + (size_t)(r0 + 8) * DST + cc) = __floats2half2_rn(v2, v3);
        }
    }
}

// -------- kernel 0: weight transpose/convert to fp16 --------
__global__ void prep_weights(const float* __restrict__ w1, const float* __restrict__ w2,
                             const float* __restrict__ w3, const float* __restrict__ fwin,
                             const float* __restrict__ fwout) {
    int i = blockIdx.x * 256 + threadIdx.x;
    if (i < 65536) {
        int h = i >> 9, k = i & 511;
        float v = (k < 384) ? w1[(128 + k) * 128 + h] : w1[(k - 384) * 128 + h];
        g_w1T[i] = __float2half(v);
    } else if (i < 81920) {
        int j = i - 65536; int h = j >> 7, k = j & 127;
        g_w2T[j] = __float2half(w2[k * 128 + h]);
    } else if (i < 98304) {
        int j = i - 81920; int h = j >> 7, k = j & 127;
        g_w3T[j] = __float2half(w3[k * 128 + h]);
    } else if (i < 163840) {
        int j = i - 98304; int f = j >> 7, k = j & 127;
        g_fwInT[j] = __float2half(fwin[k * 512 + f]);
    } else if (i < 229376) {
        int j = i - 163840; int h = j >> 9, k = j & 511;
        g_fwOutT[j] = __float2half(fwout[k * 128 + h]);
    }
}

// -------- kernel 1: message MLP + mask + K-sum + residual + LN1 --------
// CTA = 4 nodes = 192 h_e rows. 256 threads = 8 warps (4 node-warps x 2 col-halves).
// GEMM1 K streamed in 4 chunks of 128 (chunks 0-2 pure h_e, chunk 3 pure h_v).
// smem: sA/sM [192][136] f16 at 0 (52224 B; sA aliased by sM after GEMM1),
//       sB [128][136] f16 at 52224 (34816 B, shared by GEMM1 B / w2T / w3T),
//       sHv @87040 (2048), sMask @89088 (768), sDh @89856 (2048) -> 91904, 2 CTAs/SM.
#define K1_SMEM 91904
__global__ void __launch_bounds__(256, 2) k1_msg(
    const float* __restrict__ h_v, const float* __restrict__ h_e,
    const float* __restrict__ mask_attend,
    const float* __restrict__ w1_b, const float* __restrict__ w2_b,
    const float* __restrict__ w3_b,
    const float* __restrict__ ln1_g, const float* __restrict__ ln1_b) {
    extern __shared__ char smem[];
    __half* sA    = (__half*)smem;                    // [192][136] (GEMM1 A chunk)
    __half* sM    = (__half*)smem;                    // [192][136] (after GEMM1)
    __half* sB    = (__half*)(smem + 52224);          // [128][136]
    float*  sHv   = (float*)(smem + 87040);           // 512 f
    float*  sMask = (float*)(smem + 89088);           // 192 f
    float*  sDh   = (float*)(smem + 89856);           // 512 f

    const int tid = threadIdx.x, lane = tid & 31, wid = tid >> 5;
    const int wm = wid & 3, wn = wid >> 2;
    const int rowBase = wm * 48, colBase = wn * 64;
    const size_t tileRow = (size_t)blockIdx.x * 192;
    const int nodeBase = blockIdx.x * 4;

    for (int i = tid; i < 512; i += 256) sHv[i]   = h_v[(size_t)nodeBase * 128 + i];
    for (int i = tid; i < 192; i += 256) sMask[i] = mask_attend[tileRow + i];
    __syncthreads();

    float acc[3][8][4];
#pragma unroll
    for (int a = 0; a < 3; a++)
#pragma unroll
        for (int b = 0; b < 8; b++)
#pragma unroll
            for (int c = 0; c < 4; c++) acc[a][b][c] = 0.f;

    // ---- GEMM1: [192 x 512] x [512 -> 128], K in 4 chunks of 128 ----
    const float4* heBase = (const float4*)(h_e + tileRow * CIN);
    for (int kc = 0; kc < 4; ++kc) {
        if (kc < 3) {
            // A chunk from h_e: 192 rows x 32 float4 (128 f32) each, branch-free
#pragma unroll
            for (int i = 0; i < 24; ++i) {
                int idx = tid + i * 256;          // < 6144
                int r = idx >> 5, c4 = idx & 31;
                float4 v = __ldcs(heBase + (size_t)r * 96 + kc * 32 + c4);
                __half2* p = (__half2*)(sA + r * 136 + c4 * 4);
                p[0] = __floats2half2_rn(v.x, v.y);
                p[1] = __floats2half2_rn(v.z, v.w);
            }
        } else {
            // A chunk = h_v broadcast (concat columns 384..511)
#pragma unroll
            for (int i = 0; i < 24; ++i) {
                int idx = tid + i * 256;
                int r = idx >> 5, c4 = idx & 31;
                float4 v = *(const float4*)(sHv + (r / 48) * 128 + c4 * 4);
                __half2* p = (__half2*)(sA + r * 136 + c4 * 4);
                p[0] = __floats2half2_rn(v.x, v.y);
                p[1] = __floats2half2_rn(v.z, v.w);
            }
        }
        // B chunk: w1T columns [kc*128, kc*128+128)
#pragma unroll
        for (int i = 0; i < 8; ++i) {
            int idx = tid + i * 256;              // < 2048
            int n = idx >> 4, j = idx & 15;
            *(uint4*)(sB + n * 136 + j * 8) =
                *(const uint4*)(g_w1T + n * 512 + kc * 128 + j * 8);
        }
        __syncthreads();
        gemm_tile<8, 3, 4, 136, 136>(sA, sB, rowBase, colBase, lane, acc);
        __syncthreads();
    }

    // epilogue 1: +b1, gelu -> sM (overwrites dead sA) ; stage w2T -> sB
    epi_gelu_store<3, 8, 136>(acc, w1_b, sM, rowBase, colBase, lane);
#pragma unroll
    for (int i = 0; i < 8; ++i) {
        int idx = tid + i * 256;
        int n = idx >> 4, j = idx & 15;
        *(uint4*)(sB + n * 136 + j * 8) = *(const uint4*)(g_w2T + n * 128 + j * 8);
    }
    __syncthreads();

    // ---- GEMM2: [192 x 128] x [128 -> 128] ----
#pragma unroll
    for (int a = 0; a < 3; a++)
#pragma unroll
        for (int b = 0; b < 8; b++)
#pragma unroll
            for (int c = 0; c < 4; c++) acc[a][b][c] = 0.f;
    gemm_tile<8, 3, 4, 136, 136>(sM, sB, rowBase, colBase, lane, acc);
    __syncthreads();

    epi_gelu_store<3, 8, 136>(acc, w2_b, sM, rowBase, colBase, lane);
#pragma unroll
    for (int i = 0; i < 8; ++i) {
        int idx = tid + i * 256;
        int n = idx >> 4, j = idx & 15;
        *(uint4*)(sB + n * 136 + j * 8) = *(const uint4*)(g_w3T + n * 128 + j * 8);
    }
    __syncthreads();

    // ---- GEMM3 ----
#pragma unroll
    for (int a = 0; a < 3; a++)
#pragma unroll
        for (int b = 0; b < 8; b++)
#pragma unroll
            for (int c = 0; c < 4; c++) acc[a][b][c] = 0.f;
    gemm_tile<8, 3, 4, 136, 136>(sM, sB, rowBase, colBase, lane, acc);

    // epilogue 3: +b3, * mask_attend, warp-local sum over the node's 48 rows
    {
        const int g = lane >> 2, tg = lane & 3;
        float mk0[3], mk1[3];
#pragma unroll
        for (int mt = 0; mt < 3; ++mt) {
            mk0[mt] = sMask[rowBase + mt * 16 + g];
            mk1[mt] = sMask[rowBase + mt * 16 + 8 + g];
        }
#pragma unroll
        for (int nt = 0; nt < 8; ++nt) {
            const int cc = colBase + nt * 8 + tg * 2;
            const float2 b3 = __ldg((const float2*)(w3_b + cc));
            float s0 = 0.f, s1 = 0.f;
#pragma unroll
            for (int mt = 0; mt < 3; ++mt) {
                s0 += (acc[mt][nt][0] + b3.x) * mk0[mt] + (acc[mt][nt][2] + b3.x) * mk1[mt];
                s1 += (acc[mt][nt][1] + b3.y) * mk0[mt] + (acc[mt][nt][3] + b3.y) * mk1[mt];
            }
#pragma unroll
            for (int o = 4; o <= 16; o <<= 1) {
                s0 += __shfl_xor_sync(0xffffffffu, s0, o);
                s1 += __shfl_xor_sync(0xffffffffu, s1, o);
            }
            if (g == 0) *(float2*)(sDh + wm * 128 + cc) = make_float2(s0, s1);
        }
    }
    __syncthreads();

    // LN1: warps 0..3, one node each
    if (wid < 4) {
        const int node = wid;
        float x[4], sum = 0.f;
#pragma unroll
        for (int j = 0; j < 4; ++j) {
            int c = lane + 32 * j;
            x[j] = sHv[node * 128 + c] + sDh[node * 128 + c] * (1.0f / 30.0f);
            sum += x[j];
        }
#pragma unroll
        for (int o = 16; o >= 1; o >>= 1) sum += __shfl_xor_sync(0xffffffffu, sum, o);
        float mu = sum * (1.0f / 128.0f);
        float vs = 0.f;
#pragma unroll
        for (int j = 0; j < 4; ++j) { float d = x[j] - mu; vs += d * d; }
#pragma unroll
        for (int o = 16; o >= 1; o >>= 1) vs += __shfl_xor_sync(0xffffffffu, vs, o);
        float rs = rsqrtf(vs * (1.0f / 128.0f) + 1e-5f);
#pragma unroll
        for (int j = 0; j < 4; ++j) {
            int c = lane + 32 * j;
            g_h1[(size_t)(nodeBase + node) * 128 + c] =
                (x[j] - mu) * rs * __ldg(ln1_g + c) + __ldg(ln1_b + c);
        }
    }
}

// -------- kernel 2: FFN + residual + LN2 + mask_v (proven, unchanged) --------
#define K2_SW 0
#define K2_SF 139264
#define K2_SH 155904
#define K2_SX 160256
#define K2_SMEM 168704
__global__ void __launch_bounds__(256) k2_ffn(
    const float* __restrict__ mask_v,
    const float* __restrict__ fw_in_b, const float* __restrict__ fw_out_b,
    const float* __restrict__ ln2_g, const float* __restrict__ ln2_b,
    float* __restrict__ out) {
    extern __shared__ char smem[];
    __half* sW = (__half*)(smem + K2_SW);
    __half* sF = (__half*)(smem + K2_SF);
    __half* sH = (__half*)(smem + K2_SH);
    float*  sX = (float*)(smem + K2_SX);

    const int tid = threadIdx.x, lane = tid & 31, wid = tid >> 5;
    const int node0 = blockIdx.x * 16;

    for (int i = tid; i < 2048; i += 256) {
        int r = i >> 7, c = i & 127;
        sH[r * 136 + c] = __float2half(g_h1[(size_t)(node0 + r) * 128 + c]);
    }
    for (int i = tid; i < 8192; i += 256) {
        int n = i >> 4, j = i & 15;
        *(uint4*)(sW + n * 136 + j * 8) = *(const uint4*)(g_fwInT + n * 128 + j * 8);
    }
    __syncthreads();
    {
        float acc[1][8][4];
#pragma unroll
        for (int b = 0; b < 8; b++)
#pragma unroll
            for (int c = 0; c < 4; c++) acc[0][b][c] = 0.f;
        gemm_tile<8, 1, 4, 136, 136>(sH, sW, 0, wid * 64, lane, acc);
        __syncthreads();
        epi_gelu_store<1, 8, 520>(acc, fw_in_b, sF, 0, wid * 64, lane);
    }
    for (int i = tid; i < 8192; i += 256) {
        int n = i >> 6, j = i & 63;
        *(uint4*)(sW + n * 520 + j * 8) = *(const uint4*)(g_fwOutT + n * 512 + j * 8);
    }
    __syncthreads();
    {
        float acc[1][2][4];
#pragma unroll
        for (int b = 0; b < 2; b++)
#pragma unroll
            for (int c = 0; c < 4; c++) acc[0][b][c] = 0.f;
        gemm_tile<32, 1, 1, 520, 520>(sF, sW, 0, wid * 16, lane, acc);
        const int g = lane >> 2, tg = lane & 3;
#pragma unroll
        for (int nt = 0; nt < 2; ++nt) {
            const int cc = wid * 16 + nt * 8 + tg * 2;
            const float2 b = __ldg((const float2*)(fw_out_b + cc));
            const float2 r0 = *(const float2*)(g_h1 + (size_t)(node0 + g) * 128 + cc);
            const float2 r1 = *(const float2*)(g_h1 + (size_t)(node0 + 8 + g) * 128 + cc);
            sX[g * 132 + cc]           = acc[0][nt][0] + b.x + r0.x;
            sX[g * 132 + cc + 1]       = acc[0][nt][1] + b.y + r0.y;
            sX[(g + 8) * 132 + cc]     = acc[0][nt][2] + b.x + r1.x;
            sX[(g + 8) * 132 + cc + 1] = acc[0][nt][3] + b.y + r1.y;
        }
    }
    __syncthreads();
#pragma unroll
    for (int rr = 0; rr < 2; ++rr) {
        const int r = wid * 2 + rr;
        float x[4], sum = 0.f;
#pragma unroll
        for (int j = 0; j < 4; ++j) { x[j] = sX[r * 132 + lane + 32 * j]; sum += x[j]; }
#pragma unroll
        for (int o = 16; o >= 1; o >>= 1) sum += __shfl_xor_sync(0xffffffffu, sum, o);
        float mu = sum * (1.0f / 128.0f);
        float vs = 0.f;
#pragma unroll
        for (int j = 0; j < 4; ++j) { float d = x[j] - mu; vs += d * d; }
#pragma unroll
        for (int o = 16; o >= 1; o >>= 1) vs += __shfl_xor_sync(0xffffffffu, vs, o);
        float rs = rsqrtf(vs * (1.0f / 128.0f) + 1e-5f);
        float mv = mask_v[node0 + r];
#pragma unroll
        for (int j = 0; j < 4; ++j) {
            int c = lane + 32 * j;
            out[(size_t)(node0 + r) * 128 + c] =
                ((x[j] - mu) * rs * __ldg(ln2_g + c) + __ldg(ln2_b + c)) * mv;
        }
    }
}

// -------- launcher --------
extern "C" void kernel_launch(void* const* d_in, const int* in_sizes, int n_in,
                              void* d_out, int out_size) {
    const float* h_v         = (const float*)d_in[0];
    const float* h_e         = (const float*)d_in[1];
    const float* mask_v      = (const float*)d_in[2];
    const float* mask_attend = (const float*)d_in[3];
    const float* w1_b        = (const float*)d_in[5];
    const float* w2_b        = (const float*)d_in[7];
    const float* w3_b        = (const float*)d_in[9];
    const float* ln1_g       = (const float*)d_in[10];
    const float* ln1_b       = (const float*)d_in[11];
    const float* ln2_g       = (const float*)d_in[12];
    const float* ln2_b       = (const float*)d_in[13];
    const float* fw_in_b     = (const float*)d_in[15];
    const float* fw_out_b    = (const float*)d_in[17];
    float* out = (float*)d_out;

    static bool attr_done = false;
    if (!attr_done) {
        cudaFuncSetAttribute(k1_msg, cudaFuncAttributeMaxDynamicSharedMemorySize, K1_SMEM);
        cudaFuncSetAttribute(k2_ffn, cudaFuncAttributeMaxDynamicSharedMemorySize, K2_SMEM);
        attr_done = true;
    }

    prep_weights<<<896, 256>>>((const float*)d_in[4], (const float*)d_in[6],
                               (const float*)d_in[8], (const float*)d_in[14],
                               (const float*)d_in[16]);
    k1_msg<<<NNODES / 4, 256, K1_SMEM>>>(h_v, h_e, mask_attend,
                                         w1_b, w2_b, w3_b, ln1_g, ln1_b);
    k2_ffn<<<NNODES / 16, 256, K2_SMEM>>>(mask_v, fw_in_b, fw_out_b,
                                          ln2_g, ln2_b, out);
}

// round 15
// speedup vs baseline: 1.5924x; 1.0274x over previous
#include <cuda_runtime.h>
#include <cuda_fp16.h>
#include <cstdint>

#define DEVFN __device__ __forceinline__

#define NNODES 8192
#define HDIM   128
#define CIN    384
#define KTOT   512
#define FFD    512

// -------- persistent scratch --------
__device__ __half g_w1T[HDIM * KTOT];    // [h][k]: k<384 -> h_e part (cols 384+ unused now)
__device__ __half g_w2T[HDIM * HDIM];
__device__ __half g_w3T[HDIM * HDIM];
__device__ __half g_fwInT[FFD * HDIM];
__device__ __half g_fwOutT[HDIM * FFD];
__device__ float  g_h1[NNODES * HDIM];
__device__ float  g_u[NNODES * HDIM];    // h_v @ w1[0:128] per node (f32)

// -------- helpers --------
DEVFN uint32_t smaddr(const void* p) { return (uint32_t)__cvta_generic_to_shared(p); }

DEVFN void ldmx4(uint32_t addr, uint32_t& r0, uint32_t& r1, uint32_t& r2, uint32_t& r3) {
    asm volatile("ldmatrix.sync.aligned.m8n8.x4.shared.b16 {%0,%1,%2,%3}, [%4];\n"
                 : "=r"(r0), "=r"(r1), "=r"(r2), "=r"(r3) : "r"(addr));
}

DEVFN void mma16816(float (&c)[4], const uint32_t (&a)[4], uint32_t b0, uint32_t b1) {
    asm volatile(
        "mma.sync.aligned.m16n8k16.row.col.f32.f16.f16.f32 "
        "{%0,%1,%2,%3}, {%4,%5,%6,%7}, {%8,%9}, {%0,%1,%2,%3};\n"
        : "+f"(c[0]), "+f"(c[1]), "+f"(c[2]), "+f"(c[3])
        : "r"(a[0]), "r"(a[1]), "r"(a[2]), "r"(a[3]), "r"(b0), "r"(b1));
}

DEVFN float gelu_f(float x) { return 0.5f * x * (1.0f + erff(x * 0.70710678118654752f)); }

// fp16 warp-tile GEMM (A/B k-contiguous, strides in halves)
template <int KSTEPS, int MTILES, int PT, int AST, int BST>
DEVFN void gemm_tile(const __half* sAp, const __half* sBp, int rowBase, int colBase,
                     int lane, float (&acc)[MTILES][2 * PT][4]) {
    const int lr = lane & 15;
    const int lc = (lane >> 4) * 8;
#pragma unroll
    for (int ks = 0; ks < KSTEPS; ++ks) {
        const int kk = ks * 16 + lc;
        uint32_t a[MTILES][4];
#pragma unroll
        for (int mt = 0; mt < MTILES; ++mt)
            ldmx4(smaddr(sAp + (size_t)(rowBase + mt * 16 + lr) * AST + kk),
                  a[mt][0], a[mt][1], a[mt][2], a[mt][3]);
#pragma unroll
        for (int p = 0; p < PT; ++p) {
            uint32_t b0, b1, b2, b3;
            ldmx4(smaddr(sBp + (size_t)(colBase + p * 16 + lr) * BST + kk), b0, b1, b2, b3);
#pragma unroll
            for (int mt = 0; mt < MTILES; ++mt) {
                mma16816(acc[mt][2 * p],     a[mt], b0, b2);
                mma16816(acc[mt][2 * p + 1], a[mt], b1, b3);
            }
        }
    }
}

template <int MTILES, int NT, int DST>
DEVFN void epi_gelu_store(float (&acc)[MTILES][NT][4], const float* __restrict__ bias,
                          __half* dst, int rowBase, int colBase, int lane) {
    const int g = lane >> 2, tg = lane & 3;
#pragma unroll
    for (int mt = 0; mt < MTILES; ++mt) {
        const int r0 = rowBase + mt * 16 + g;
#pragma unroll
        for (int nt = 0; nt < NT; ++nt) {
            const int cc = colBase + nt * 8 + tg * 2;
            const float2 b = __ldg((const float2*)(bias + cc));
            float v0 = gelu_f(acc[mt][nt][0] + b.x);
            float v1 = gelu_f(acc[mt][nt][1] + b.y);
            float v2 = gelu_f(acc[mt][nt][2] + b.x);
            float v3 = gelu_f(acc[mt][nt][3] + b.y);
            *(__half2*)(dst + (size_t)r0 * DST + cc)       = __floats2half2_rn(v0, v1);
            *(__half2*)(dst + (size_t)(r0 + 8) * DST + cc) = __floats2half2_rn(v2, v3);
        }
    }
}

// -------- kernel 0a: weight transpose/convert to fp16 --------
__global__ void prep_weights(const float* __restrict__ w1, const float* __restrict__ w2,
                             const float* __restrict__ w3, const float* __restrict__ fwin,
                             const float* __restrict__ fwout) {
    int i = blockIdx.x * 256 + threadIdx.x;
    if (i < 65536) {
        int h = i >> 9, k = i & 511;
        float v = (k < 384) ? w1[(128 + k) * 128 + h] : w1[(k - 384) * 128 + h];
        g_w1T[i] = __float2half(v);
    } else if (i < 81920) {
        int j = i - 65536; int h = j >> 7, k = j & 127;
        g_w2T[j] = __float2half(w2[k * 128 + h]);
    } else if (i < 98304) {
        int j = i - 81920; int h = j >> 7, k = j & 127;
        g_w3T[j] = __float2half(w3[k * 128 + h]);
    } else if (i < 163840) {
        int j = i - 98304; int f = j >> 7, k = j & 127;
        g_fwInT[j] = __float2half(fwin[k * 512 + f]);
    } else if (i < 229376) {
        int j = i - 163840; int h = j >> 9, k = j & 511;
        g_fwOutT[j] = __float2half(fwout[k * 128 + h]);
    }
}

// -------- kernel 0b: u[n] = h_v[n] @ w1[0:128] (exact f32, once per node) --------
// block = 16 nodes, 256 threads: thread (g = tid>>7, h = tid&127) accumulates
// nodes g*8..g*8+7 for output column h.
__global__ void __launch_bounds__(256) prep_hv(const float* __restrict__ h_v,
                                               const float* __restrict__ w1) {
    __shared__ float sW[32 * 128];   // w1 rows chunk (k-major)
    __shared__ float sV[16 * 32];    // h_v chunk [node][k]
    const int tid = threadIdx.x;
    const int h = tid & 127, g = tid >> 7;
    const int node0 = blockIdx.x * 16;
    float acc[8];
#pragma unroll
    for (int i = 0; i < 8; ++i) acc[i] = 0.f;
    for (int kc = 0; kc < 4; ++kc) {
        for (int i = tid; i < 4096; i += 256) {
            int k = i >> 7, c = i & 127;
            sW[k * 128 + c] = w1[(kc * 32 + k) * 128 + c];
        }
        for (int i = tid; i < 512; i += 256) {
            int n = i >> 5, k = i & 31;
            sV[n * 32 + k] = h_v[(size_t)(node0 + n) * 128 + kc * 32 + k];
        }
        __syncthreads();
#pragma unroll 8
        for (int k = 0; k < 32; ++k) {
            float w = sW[k * 128 + h];
#pragma unroll
            for (int i = 0; i < 8; ++i) acc[i] += sV[(g * 8 + i) * 32 + k] * w;
        }
        __syncthreads();
    }
#pragma unroll
    for (int i = 0; i < 8; ++i)
        g_u[(size_t)(node0 + g * 8 + i) * 128 + h] = acc[i];
}

// -------- kernel 1: message MLP + mask + K-sum + residual + LN1 --------
// CTA = 4 nodes = 192 h_e rows. 256 threads = 8 warps (4 node-warps x 2 col-halves).
// GEMM1: K = 384 (h_e only; h_v part hoisted into per-node u), 3 chunks of 128.
// smem: sA/sM [192][136] f16 @0 (52224), sB [128][136] @52224 (34816),
//       sHv @87040 (2048), sMask @89088 (768), sDh @89856 (2048), sU @91904 (2048)
//       -> 93952 B, 2 CTAs/SM.
#define K1_SMEM 93952
__global__ void __launch_bounds__(256, 2) k1_msg(
    const float* __restrict__ h_v, const float* __restrict__ h_e,
    const float* __restrict__ mask_attend,
    const float* __restrict__ w1_b, const float* __restrict__ w2_b,
    const float* __restrict__ w3_b,
    const float* __restrict__ ln1_g, const float* __restrict__ ln1_b) {
    extern __shared__ char smem[];
    __half* sA    = (__half*)smem;                    // [192][136] (GEMM1 A chunk)
    __half* sM    = (__half*)smem;                    // [192][136] (after GEMM1)
    __half* sB    = (__half*)(smem + 52224);          // [128][136]
    float*  sHv   = (float*)(smem + 87040);           // 512 f
    float*  sMask = (float*)(smem + 89088);           // 192 f
    float*  sDh   = (float*)(smem + 89856);           // 512 f
    float*  sU    = (float*)(smem + 91904);           // 512 f

    const int tid = threadIdx.x, lane = tid & 31, wid = tid >> 5;
    const int wm = wid & 3, wn = wid >> 2;
    const int rowBase = wm * 48, colBase = wn * 64;
    const size_t tileRow = (size_t)blockIdx.x * 192;
    const int nodeBase = blockIdx.x * 4;

    for (int i = tid; i < 512; i += 256) {
        sHv[i] = h_v[(size_t)nodeBase * 128 + i];
        sU[i]  = g_u[(size_t)nodeBase * 128 + i];
    }
    for (int i = tid; i < 192; i += 256) sMask[i] = mask_attend[tileRow + i];
    __syncthreads();

    float acc[3][8][4];
#pragma unroll
    for (int a = 0; a < 3; a++)
#pragma unroll
        for (int b = 0; b < 8; b++)
#pragma unroll
            for (int c = 0; c < 4; c++) acc[a][b][c] = 0.f;

    // ---- GEMM1: [192 x 384] x [384 -> 128], K in 3 chunks of 128 (pure h_e) ----
    const float4* heBase = (const float4*)(h_e + tileRow * CIN);
    for (int kc = 0; kc < 3; ++kc) {
#pragma unroll
        for (int i = 0; i < 24; ++i) {
            int idx = tid + i * 256;          // < 6144
            int r = idx >> 5, c4 = idx & 31;
            float4 v = __ldcs(heBase + (size_t)r * 96 + kc * 32 + c4);
            __half2* p = (__half2*)(sA + r * 136 + c4 * 4);
            p[0] = __floats2half2_rn(v.x, v.y);
            p[1] = __floats2half2_rn(v.z, v.w);
        }
#pragma unroll
        for (int i = 0; i < 8; ++i) {
            int idx = tid + i * 256;              // < 2048
            int n = idx >> 4, j = idx & 15;
            *(uint4*)(sB + n * 136 + j * 8) =
                *(const uint4*)(g_w1T + n * 512 + kc * 128 + j * 8);
        }
        __syncthreads();
        gemm_tile<8, 3, 4, 136, 136>(sA, sB, rowBase, colBase, lane, acc);
        __syncthreads();
    }

    // epilogue 1: + b1 + u[node], gelu -> sM (overwrites dead sA); stage w2T -> sB
    {
        const int g = lane >> 2, tg = lane & 3;
        const float* uRow = sU + wm * 128;
#pragma unroll
        for (int mt = 0; mt < 3; ++mt) {
            const int r0 = rowBase + mt * 16 + g;
#pragma unroll
            for (int nt = 0; nt < 8; ++nt) {
                const int cc = colBase + nt * 8 + tg * 2;
                const float2 b = __ldg((const float2*)(w1_b + cc));
                const float2 u = *(const float2*)(uRow + cc);
                float v0 = gelu_f(acc[mt][nt][0] + b.x + u.x);
                float v1 = gelu_f(acc[mt][nt][1] + b.y + u.y);
                float v2 = gelu_f(acc[mt][nt][2] + b.x + u.x);
                float v3 = gelu_f(acc[mt][nt][3] + b.y + u.y);
                *(__half2*)(sM + (size_t)r0 * 136 + cc)       = __floats2half2_rn(v0, v1);
                *(__half2*)(sM + (size_t)(r0 + 8) * 136 + cc) = __floats2half2_rn(v2, v3);
            }
        }
    }
#pragma unroll
    for (int i = 0; i < 8; ++i) {
        int idx = tid + i * 256;
        int n = idx >> 4, j = idx & 15;
        *(uint4*)(sB + n * 136 + j * 8) = *(const uint4*)(g_w2T + n * 128 + j * 8);
    }
    __syncthreads();

    // ---- GEMM2: [192 x 128] x [128 -> 128] ----
#pragma unroll
    for (int a = 0; a < 3; a++)
#pragma unroll
        for (int b = 0; b < 8; b++)
#pragma unroll
            for (int c = 0; c < 4; c++) acc[a][b][c] = 0.f;
    gemm_tile<8, 3, 4, 136, 136>(sM, sB, rowBase, colBase, lane, acc);
    __syncthreads();

    epi_gelu_store<3, 8, 136>(acc, w2_b, sM, rowBase, colBase, lane);
#pragma unroll
    for (int i = 0; i < 8; ++i) {
        int idx = tid + i * 256;
        int n = idx >> 4, j = idx & 15;
        *(uint4*)(sB + n * 136 + j * 8) = *(const uint4*)(g_w3T + n * 128 + j * 8);
    }
    __syncthreads();

    // ---- GEMM3 ----
#pragma unroll
    for (int a = 0; a < 3; a++)
#pragma unroll
        for (int b = 0; b < 8; b++)
#pragma unroll
            for (int c = 0; c < 4; c++) acc[a][b][c] = 0.f;
    gemm_tile<8, 3, 4, 136, 136>(sM, sB, rowBase, colBase, lane, acc);

    // epilogue 3: +b3, * mask_attend, warp-local sum over the node's 48 rows
    {
        const int g = lane >> 2, tg = lane & 3;
        float mk0[3], mk1[3];
#pragma unroll
        for (int mt = 0; mt < 3; ++mt) {
            mk0[mt] = sMask[rowBase + mt * 16 + g];
            mk1[mt] = sMask[rowBase + mt * 16 + 8 + g];
        }
#pragma unroll
        for (int nt = 0; nt < 8; ++nt) {
            const int cc = colBase + nt * 8 + tg * 2;
            const float2 b3 = __ldg((const float2*)(w3_b + cc));
            float s0 = 0.f, s1 = 0.f;
#pragma unroll
            for (int mt = 0; mt < 3; ++mt) {
                s0 += (acc[mt][nt][0] + b3.x) * mk0[mt] + (acc[mt][nt][2] + b3.x) * mk1[mt];
                s1 += (acc[mt][nt][1] + b3.y) * mk0[mt] + (acc[mt][nt][3] + b3.y) * mk1[mt];
            }
#pragma unroll
            for (int o = 4; o <= 16; o <<= 1) {
                s0 += __shfl_xor_sync(0xffffffffu, s0, o);
                s1 += __shfl_xor_sync(0xffffffffu, s1, o);
            }
            if (g == 0) *(float2*)(sDh + wm * 128 + cc) = make_float2(s0, s1);
        }
    }
    __syncthreads();

    // LN1: warps 0..3, one node each
    if (wid < 4) {
        const int node = wid;
        float x[4], sum = 0.f;
#pragma unroll
        for (int j = 0; j < 4; ++j) {
            int c = lane + 32 * j;
            x[j] = sHv[node * 128 + c] + sDh[node * 128 + c] * (1.0f / 30.0f);
            sum += x[j];
        }
#pragma unroll
        for (int o = 16; o >= 1; o >>= 1) sum += __shfl_xor_sync(0xffffffffu, sum, o);
        float mu = sum * (1.0f / 128.0f);
        float vs = 0.f;
#pragma unroll
        for (int j = 0; j < 4; ++j) { float d = x[j] - mu; vs += d * d; }
#pragma unroll
        for (int o = 16; o >= 1; o >>= 1) vs += __shfl_xor_sync(0xffffffffu, vs, o);
        float rs = rsqrtf(vs * (1.0f / 128.0f) + 1e-5f);
#pragma unroll
        for (int j = 0; j < 4; ++j) {
            int c = lane + 32 * j;
            g_h1[(size_t)(nodeBase + node) * 128 + c] =
                (x[j] - mu) * rs * __ldg(ln1_g + c) + __ldg(ln1_b + c);
        }
    }
}

// -------- kernel 2: FFN + residual + LN2 + mask_v (proven, unchanged) --------
#define K2_SW 0
#define K2_SF 139264
#define K2_SH 155904
#define K2_SX 160256
#define K2_SMEM 168704
__global__ void __launch_bounds__(256) k2_ffn(
    const float* __restrict__ mask_v,
    const float* __restrict__ fw_in_b, const float* __restrict__ fw_out_b,
    const float* __restrict__ ln2_g, const float* __restrict__ ln2_b,
    float* __restrict__ out) {
    extern __shared__ char smem[];
    __half* sW = (__half*)(smem + K2_SW);
    __half* sF = (__half*)(smem + K2_SF);
    __half* sH = (__half*)(smem + K2_SH);
    float*  sX = (float*)(smem + K2_SX);

    const int tid = threadIdx.x, lane = tid & 31, wid = tid >> 5;
    const int node0 = blockIdx.x * 16;

    for (int i = tid; i < 2048; i += 256) {
        int r = i >> 7, c = i & 127;
        sH[r * 136 + c] = __float2half(g_h1[(size_t)(node0 + r) * 128 + c]);
    }
    for (int i = tid; i < 8192; i += 256) {
        int n = i >> 4, j = i & 15;
        *(uint4*)(sW + n * 136 + j * 8) = *(const uint4*)(g_fwInT + n * 128 + j * 8);
    }
    __syncthreads();
    {
        float acc[1][8][4];
#pragma unroll
        for (int b = 0; b < 8; b++)
#pragma unroll
            for (int c = 0; c < 4; c++) acc[0][b][c] = 0.f;
        gemm_tile<8, 1, 4, 136, 136>(sH, sW, 0, wid * 64, lane, acc);
        __syncthreads();
        epi_gelu_store<1, 8, 520>(acc, fw_in_b, sF, 0, wid * 64, lane);
    }
    for (int i = tid; i < 8192; i += 256) {
        int n = i >> 6, j = i & 63;
        *(uint4*)(sW + n * 520 + j * 8) = *(const uint4*)(g_fwOutT + n * 512 + j * 8);
    }
    __syncthreads();
    {
        float acc[1][2][4];
#pragma unroll
        for (int b = 0; b < 2; b++)
#pragma unroll
            for (int c = 0; c < 4; c++) acc[0][b][c] = 0.f;
        gemm_tile<32, 1, 1, 520, 520>(sF, sW, 0, wid * 16, lane, acc);
        const int g = lane >> 2, tg = lane & 3;
#pragma unroll
        for (int nt = 0; nt < 2; ++nt) {
            const int cc = wid * 16 + nt * 8 + tg * 2;
            const float2 b = __ldg((const float2*)(fw_out_b + cc));
            const float2 r0 = *(const float2*)(g_h1 + (size_t)(node0 + g) * 128 + cc);
            const float2 r1 = *(const float2*)(g_h1 + (size_t)(node0 + 8 + g) * 128 + cc);
            sX[g * 132 + cc]           = acc[0][nt][0] + b.x + r0.x;
            sX[g * 132 + cc + 1]       = acc[0][nt][1] + b.y + r0.y;
            sX[(g + 8) * 132 + cc]     = acc[0][nt][2] + b.x + r1.x;
            sX[(g + 8) * 132 + cc + 1] = acc[0][nt][3] + b.y + r1.y;
        }
    }
    __syncthreads();
#pragma unroll
    for (int rr = 0; rr < 2; ++rr) {
        const int r = wid * 2 + rr;
        float x[4], sum = 0.f;
#pragma unroll
        for (int j = 0; j < 4; ++j) { x[j] = sX[r * 132 + lane + 32 * j]; sum += x[j]; }
#pragma unroll
        for (int o = 16; o >= 1; o >>= 1) sum += __shfl_xor_sync(0xffffffffu, sum, o);
        float mu = sum * (1.0f / 128.0f);
        float vs = 0.f;
#pragma unroll
        for (int j = 0; j < 4; ++j) { float d = x[j] - mu; vs += d * d; }
#pragma unroll
        for (int o = 16; o >= 1; o >>= 1) vs += __shfl_xor_sync(0xffffffffu, vs, o);
        float rs = rsqrtf(vs * (1.0f / 128.0f) + 1e-5f);
        float mv = mask_v[node0 + r];
#pragma unroll
        for (int j = 0; j < 4; ++j) {
            int c = lane + 32 * j;
            out[(size_t)(node0 + r) * 128 + c] =
                ((x[j] - mu) * rs * __ldg(ln2_g + c) + __ldg(ln2_b + c)) * mv;
        }
    }
}

// -------- launcher --------
extern "C" void kernel_launch(void* const* d_in, const int* in_sizes, int n_in,
                              void* d_out, int out_size) {
    const float* h_v         = (const float*)d_in[0];
    const float* h_e         = (const float*)d_in[1];
    const float* mask_v      = (const float*)d_in[2];
    const float* mask_attend = (const float*)d_in[3];
    const float* w1_w        = (const float*)d_in[4];
    const float* w1_b        = (const float*)d_in[5];
    const float* w2_b        = (const float*)d_in[7];
    const float* w3_b        = (const float*)d_in[9];
    const float* ln1_g       = (const float*)d_in[10];
    const float* ln1_b       = (const float*)d_in[11];
    const float* ln2_g       = (const float*)d_in[12];
    const float* ln2_b       = (const float*)d_in[13];
    const float* fw_in_b     = (const float*)d_in[15];
    const float* fw_out_b    = (const float*)d_in[17];
    float* out = (float*)d_out;

    static bool attr_done = false;
    if (!attr_done) {
        cudaFuncSetAttribute(k1_msg, cudaFuncAttributeMaxDynamicSharedMemorySize, K1_SMEM);
        cudaFuncSetAttribute(k2_ffn, cudaFuncAttributeMaxDynamicSharedMemorySize, K2_SMEM);
        attr_done = true;
    }

    prep_weights<<<896, 256>>>(w1_w, (const float*)d_in[6],
                               (const float*)d_in[8], (const float*)d_in[14],
                               (const float*)d_in[16]);
    prep_hv<<<NNODES / 16, 256>>>(h_v, w1_w);
    k1_msg<<<NNODES / 4, 256, K1_SMEM>>>(h_v, h_e, mask_attend,
                                         w1_b, w2_b, w3_b, ln1_g, ln1_b);
    k2_ffn<<<NNODES / 16, 256, K2_SMEM>>>(mask_v, fw_in_b, fw_out_b,
                                          ln2_g, ln2_b, out);
}

// round 16
// speedup vs baseline: 1.6405x; 1.0302x over previous
#include <cuda_runtime.h>
#include <cuda_fp16.h>
#include <cstdint>

#define DEVFN __device__ __forceinline__

#define NNODES 8192
#define HDIM   128
#define CIN    384
#define KTOT   512
#define FFD    512

// -------- persistent scratch --------
__device__ __half g_w1T[HDIM * KTOT];
__device__ __half g_w2T[HDIM * HDIM];
__device__ __half g_w3T[HDIM * HDIM];
__device__ __half g_fwInT[FFD * HDIM];
__device__ __half g_fwOutT[HDIM * FFD];
__device__ float  g_h1[NNODES * HDIM];
__device__ float  g_u[NNODES * HDIM];    // h_v @ w1[0:128] per node (f32)

// -------- helpers --------
DEVFN uint32_t smaddr(const void* p) { return (uint32_t)__cvta_generic_to_shared(p); }

DEVFN void ldmx4(uint32_t addr, uint32_t& r0, uint32_t& r1, uint32_t& r2, uint32_t& r3) {
    asm volatile("ldmatrix.sync.aligned.m8n8.x4.shared.b16 {%0,%1,%2,%3}, [%4];\n"
                 : "=r"(r0), "=r"(r1), "=r"(r2), "=r"(r3) : "r"(addr));
}

DEVFN void mma16816(float (&c)[4], const uint32_t (&a)[4], uint32_t b0, uint32_t b1) {
    asm volatile(
        "mma.sync.aligned.m16n8k16.row.col.f32.f16.f16.f32 "
        "{%0,%1,%2,%3}, {%4,%5,%6,%7}, {%8,%9}, {%0,%1,%2,%3};\n"
        : "+f"(c[0]), "+f"(c[1]), "+f"(c[2]), "+f"(c[3])
        : "r"(a[0]), "r"(a[1]), "r"(a[2]), "r"(a[3]), "r"(b0), "r"(b1));
}

DEVFN float gelu_f(float x) { return 0.5f * x * (1.0f + erff(x * 0.70710678118654752f)); }

// fp16 warp-tile GEMM (A/B k-contiguous, strides in halves)
template <int KSTEPS, int MTILES, int PT, int AST, int BST>
DEVFN void gemm_tile(const __half* sAp, const __half* sBp, int rowBase, int colBase,
                     int lane, float (&acc)[MTILES][2 * PT][4]) {
    const int lr = lane & 15;
    const int lc = (lane >> 4) * 8;
#pragma unroll
    for (int ks = 0; ks < KSTEPS; ++ks) {
        const int kk = ks * 16 + lc;
        uint32_t a[MTILES][4];
#pragma unroll
        for (int mt = 0; mt < MTILES; ++mt)
            ldmx4(smaddr(sAp + (size_t)(rowBase + mt * 16 + lr) * AST + kk),
                  a[mt][0], a[mt][1], a[mt][2], a[mt][3]);
#pragma unroll
        for (int p = 0; p < PT; ++p) {
            uint32_t b0, b1, b2, b3;
            ldmx4(smaddr(sBp + (size_t)(colBase + p * 16 + lr) * BST + kk), b0, b1, b2, b3);
#pragma unroll
            for (int mt = 0; mt < MTILES; ++mt) {
                mma16816(acc[mt][2 * p],     a[mt], b0, b2);
                mma16816(acc[mt][2 * p + 1], a[mt], b1, b3);
            }
        }
    }
}

template <int MTILES, int NT, int DST>
DEVFN void epi_gelu_store(float (&acc)[MTILES][NT][4], const float* __restrict__ bias,
                          __half* dst, int rowBase, int colBase, int lane) {
    const int g = lane >> 2, tg = lane & 3;
#pragma unroll
    for (int mt = 0; mt < MTILES; ++mt) {
        const int r0 = rowBase + mt * 16 + g;
#pragma unroll
        for (int nt = 0; nt < NT; ++nt) {
            const int cc = colBase + nt * 8 + tg * 2;
            const float2 b = __ldg((const float2*)(bias + cc));
            float v0 = gelu_f(acc[mt][nt][0] + b.x);
            float v1 = gelu_f(acc[mt][nt][1] + b.y);
            float v2 = gelu_f(acc[mt][nt][2] + b.x);
            float v3 = gelu_f(acc[mt][nt][3] + b.y);
            *(__half2*)(dst + (size_t)r0 * DST + cc)       = __floats2half2_rn(v0, v1);
            *(__half2*)(dst + (size_t)(r0 + 8) * DST + cc) = __floats2half2_rn(v2, v3);
        }
    }
}

// -------- kernel 0a: weight transpose/convert to fp16 --------
__global__ void prep_weights(const float* __restrict__ w1, const float* __restrict__ w2,
                             const float* __restrict__ w3, const float* __restrict__ fwin,
                             const float* __restrict__ fwout) {
    int i = blockIdx.x * 256 + threadIdx.x;
    if (i < 65536) {
        int h = i >> 9, k = i & 511;
        float v = (k < 384) ? w1[(128 + k) * 128 + h] : w1[(k - 384) * 128 + h];
        g_w1T[i] = __float2half(v);
    } else if (i < 81920) {
        int j = i - 65536; int h = j >> 7, k = j & 127;
        g_w2T[j] = __float2half(w2[k * 128 + h]);
    } else if (i < 98304) {
        int j = i - 81920; int h = j >> 7, k = j & 127;
        g_w3T[j] = __float2half(w3[k * 128 + h]);
    } else if (i < 163840) {
        int j = i - 98304; int f = j >> 7, k = j & 127;
        g_fwInT[j] = __float2half(fwin[k * 512 + f]);
    } else if (i < 229376) {
        int j = i - 163840; int h = j >> 9, k = j & 511;
        g_fwOutT[j] = __float2half(fwout[k * 128 + h]);
    }
}

// -------- kernel 0b: u[n] = h_v[n] @ w1[0:128] (exact f32) --------
__global__ void __launch_bounds__(256) prep_hv(const float* __restrict__ h_v,
                                               const float* __restrict__ w1) {
    __shared__ float sW[32 * 128];
    __shared__ float sV[16 * 32];
    const int tid = threadIdx.x;
    const int h = tid & 127, g = tid >> 7;
    const int node0 = blockIdx.x * 16;
    float acc[8];
#pragma unroll
    for (int i = 0; i < 8; ++i) acc[i] = 0.f;
    for (int kc = 0; kc < 4; ++kc) {
        for (int i = tid; i < 4096; i += 256) {
            int k = i >> 7, c = i & 127;
            sW[k * 128 + c] = w1[(kc * 32 + k) * 128 + c];
        }
        for (int i = tid; i < 512; i += 256) {
            int n = i >> 5, k = i & 31;
            sV[n * 32 + k] = h_v[(size_t)(node0 + n) * 128 + kc * 32 + k];
        }
        __syncthreads();
#pragma unroll 8
        for (int k = 0; k < 32; ++k) {
            float w = sW[k * 128 + h];
#pragma unroll
            for (int i = 0; i < 8; ++i) acc[i] += sV[(g * 8 + i) * 32 + k] * w;
        }
        __syncthreads();
    }
#pragma unroll
    for (int i = 0; i < 8; ++i)
        g_u[(size_t)(node0 + g * 8 + i) * 128 + h] = acc[i];
}

// -------- kernel 1: message MLP + mask + K-sum + residual + LN1 (proven) --------
#define K1_SMEM 93952
__global__ void __launch_bounds__(256, 2) k1_msg(
    const float* __restrict__ h_v, const float* __restrict__ h_e,
    const float* __restrict__ mask_attend,
    const float* __restrict__ w1_b, const float* __restrict__ w2_b,
    const float* __restrict__ w3_b,
    const float* __restrict__ ln1_g, const float* __restrict__ ln1_b) {
    extern __shared__ char smem[];
    __half* sA    = (__half*)smem;
    __half* sM    = (__half*)smem;
    __half* sB    = (__half*)(smem + 52224);
    float*  sHv   = (float*)(smem + 87040);
    float*  sMask = (float*)(smem + 89088);
    float*  sDh   = (float*)(smem + 89856);
    float*  sU    = (float*)(smem + 91904);

    const int tid = threadIdx.x, lane = tid & 31, wid = tid >> 5;
    const int wm = wid & 3, wn = wid >> 2;
    const int rowBase = wm * 48, colBase = wn * 64;
    const size_t tileRow = (size_t)blockIdx.x * 192;
    const int nodeBase = blockIdx.x * 4;

    for (int i = tid; i < 512; i += 256) {
        sHv[i] = h_v[(size_t)nodeBase * 128 + i];
        sU[i]  = g_u[(size_t)nodeBase * 128 + i];
    }
    for (int i = tid; i < 192; i += 256) sMask[i] = mask_attend[tileRow + i];
    __syncthreads();

    float acc[3][8][4];
#pragma unroll
    for (int a = 0; a < 3; a++)
#pragma unroll
        for (int b = 0; b < 8; b++)
#pragma unroll
            for (int c = 0; c < 4; c++) acc[a][b][c] = 0.f;

    const float4* heBase = (const float4*)(h_e + tileRow * CIN);
    for (int kc = 0; kc < 3; ++kc) {
#pragma unroll
        for (int i = 0; i < 24; ++i) {
            int idx = tid + i * 256;
            int r = idx >> 5, c4 = idx & 31;
            float4 v = __ldcs(heBase + (size_t)r * 96 + kc * 32 + c4);
            __half2* p = (__half2*)(sA + r * 136 + c4 * 4);
            p[0] = __floats2half2_rn(v.x, v.y);
            p[1] = __floats2half2_rn(v.z, v.w);
        }
#pragma unroll
        for (int i = 0; i < 8; ++i) {
            int idx = tid + i * 256;
            int n = idx >> 4, j = idx & 15;
            *(uint4*)(sB + n * 136 + j * 8) =
                *(const uint4*)(g_w1T + n * 512 + kc * 128 + j * 8);
        }
        __syncthreads();
        gemm_tile<8, 3, 4, 136, 136>(sA, sB, rowBase, colBase, lane, acc);
        __syncthreads();
    }

    // epilogue 1: + b1 + u[node], gelu -> sM; stage w2T -> sB
    {
        const int g = lane >> 2, tg = lane & 3;
        const float* uRow = sU + wm * 128;
#pragma unroll
        for (int mt = 0; mt < 3; ++mt) {
            const int r0 = rowBase + mt * 16 + g;
#pragma unroll
            for (int nt = 0; nt < 8; ++nt) {
                const int cc = colBase + nt * 8 + tg * 2;
                const float2 b = __ldg((const float2*)(w1_b + cc));
                const float2 u = *(const float2*)(uRow + cc);
                float v0 = gelu_f(acc[mt][nt][0] + b.x + u.x);
                float v1 = gelu_f(acc[mt][nt][1] + b.y + u.y);
                float v2 = gelu_f(acc[mt][nt][2] + b.x + u.x);
                float v3 = gelu_f(acc[mt][nt][3] + b.y + u.y);
                *(__half2*)(sM + (size_t)r0 * 136 + cc)       = __floats2half2_rn(v0, v1);
                *(__half2*)(sM + (size_t)(r0 + 8) * 136 + cc) = __floats2half2_rn(v2, v3);
            }
        }
    }
#pragma unroll
    for (int i = 0; i < 8; ++i) {
        int idx = tid + i * 256;
        int n = idx >> 4, j = idx & 15;
        *(uint4*)(sB + n * 136 + j * 8) = *(const uint4*)(g_w2T + n * 128 + j * 8);
    }
    __syncthreads();

#pragma unroll
    for (int a = 0; a < 3; a++)
#pragma unroll
        for (int b = 0; b < 8; b++)
#pragma unroll
            for (int c = 0; c < 4; c++) acc[a][b][c] = 0.f;
    gemm_tile<8, 3, 4, 136, 136>(sM, sB, rowBase, colBase, lane, acc);
    __syncthreads();

    epi_gelu_store<3, 8, 136>(acc, w2_b, sM, rowBase, colBase, lane);
#pragma unroll
    for (int i = 0; i < 8; ++i) {
        int idx = tid + i * 256;
        int n = idx >> 4, j = idx & 15;
        *(uint4*)(sB + n * 136 + j * 8) = *(const uint4*)(g_w3T + n * 128 + j * 8);
    }
    __syncthreads();

#pragma unroll
    for (int a = 0; a < 3; a++)
#pragma unroll
        for (int b = 0; b < 8; b++)
#pragma unroll
            for (int c = 0; c < 4; c++) acc[a][b][c] = 0.f;
    gemm_tile<8, 3, 4, 136, 136>(sM, sB, rowBase, colBase, lane, acc);

    {
        const int g = lane >> 2, tg = lane & 3;
        float mk0[3], mk1[3];
#pragma unroll
        for (int mt = 0; mt < 3; ++mt) {
            mk0[mt] = sMask[rowBase + mt * 16 + g];
            mk1[mt] = sMask[rowBase + mt * 16 + 8 + g];
        }
#pragma unroll
        for (int nt = 0; nt < 8; ++nt) {
            const int cc = colBase + nt * 8 + tg * 2;
            const float2 b3 = __ldg((const float2*)(w3_b + cc));
            float s0 = 0.f, s1 = 0.f;
#pragma unroll
            for (int mt = 0; mt < 3; ++mt) {
                s0 += (acc[mt][nt][0] + b3.x) * mk0[mt] + (acc[mt][nt][2] + b3.x) * mk1[mt];
                s1 += (acc[mt][nt][1] + b3.y) * mk0[mt] + (acc[mt][nt][3] + b3.y) * mk1[mt];
            }
#pragma unroll
            for (int o = 4; o <= 16; o <<= 1) {
                s0 += __shfl_xor_sync(0xffffffffu, s0, o);
                s1 += __shfl_xor_sync(0xffffffffu, s1, o);
            }
            if (g == 0) *(float2*)(sDh + wm * 128 + cc) = make_float2(s0, s1);
        }
    }
    __syncthreads();

    if (wid < 4) {
        const int node = wid;
        float x[4], sum = 0.f;
#pragma unroll
        for (int j = 0; j < 4; ++j) {
            int c = lane + 32 * j;
            x[j] = sHv[node * 128 + c] + sDh[node * 128 + c] * (1.0f / 30.0f);
            sum += x[j];
        }
#pragma unroll
        for (int o = 16; o >= 1; o >>= 1) sum += __shfl_xor_sync(0xffffffffu, sum, o);
        float mu = sum * (1.0f / 128.0f);
        float vs = 0.f;
#pragma unroll
        for (int j = 0; j < 4; ++j) { float d = x[j] - mu; vs += d * d; }
#pragma unroll
        for (int o = 16; o >= 1; o >>= 1) vs += __shfl_xor_sync(0xffffffffu, vs, o);
        float rs = rsqrtf(vs * (1.0f / 128.0f) + 1e-5f);
#pragma unroll
        for (int j = 0; j < 4; ++j) {
            int c = lane + 32 * j;
            g_h1[(size_t)(nodeBase + node) * 128 + c] =
                (x[j] - mu) * rs * __ldg(ln1_g + c) + __ldg(ln1_b + c);
        }
    }
}

// -------- kernel 2: FFN + residual + LN2 + mask_v --------
// REWORK: 32 nodes/CTA, 512 threads = 16 warps (2 row-halves x 8 col-slices).
// smem: sW @0 (139264 = max(512x136, 128x520) f16), sF @139264 ([32][520] f16, 33280),
//       sH @172544 ([32][136] f16, 8704), sX @181248 ([32][132] f32, 16896) -> 198144.
#define K2_SW 0
#define K2_SF 139264
#define K2_SH 172544
#define K2_SX 181248
#define K2_SMEM 198144
__global__ void __launch_bounds__(512) k2_ffn(
    const float* __restrict__ mask_v,
    const float* __restrict__ fw_in_b, const float* __restrict__ fw_out_b,
    const float* __restrict__ ln2_g, const float* __restrict__ ln2_b,
    float* __restrict__ out) {
    extern __shared__ char smem[];
    __half* sW = (__half*)(smem + K2_SW);
    __half* sF = (__half*)(smem + K2_SF);
    __half* sH = (__half*)(smem + K2_SH);
    float*  sX = (float*)(smem + K2_SX);

    const int tid = threadIdx.x, lane = tid & 31, wid = tid >> 5;
    const int wm = wid & 1, wn = wid >> 1;          // 2 row-halves x 8 col-slices
    const int node0 = blockIdx.x * 32;

    for (int i = tid; i < 4096; i += 512) {
        int r = i >> 7, c = i & 127;
        sH[r * 136 + c] = __float2half(g_h1[(size_t)(node0 + r) * 128 + c]);
    }
    for (int i = tid; i < 8192; i += 512) {
        int n = i >> 4, j = i & 15;
        *(uint4*)(sW + n * 136 + j * 8) = *(const uint4*)(g_fwInT + n * 128 + j * 8);
    }
    __syncthreads();

    // GEMM-in: [32 x 128] x [128 -> 512]; warp (wm,wn) does rows wm*16..+15, FF cols wn*64..+63
    {
        float acc[1][8][4];
#pragma unroll
        for (int b = 0; b < 8; b++)
#pragma unroll
            for (int c = 0; c < 4; c++) acc[0][b][c] = 0.f;
        gemm_tile<8, 1, 4, 136, 136>(sH, sW, wm * 16, wn * 64, lane, acc);
        __syncthreads();  // all sW reads done before overwrite
        epi_gelu_store<1, 8, 520>(acc, fw_in_b, sF, wm * 16, wn * 64, lane);
    }
    for (int i = tid; i < 8192; i += 512) {
        int n = i >> 6, j = i & 63;
        *(uint4*)(sW + n * 520 + j * 8) = *(const uint4*)(g_fwOutT + n * 512 + j * 8);
    }
    __syncthreads();

    // GEMM-out: [32 x 512] x [512 -> 128]; warp (wm,wn) does rows wm*16..+15, H cols wn*16..+15
    {
        float acc[1][2][4];
#pragma unroll
        for (int b = 0; b < 2; b++)
#pragma unroll
            for (int c = 0; c < 4; c++) acc[0][b][c] = 0.f;
        gemm_tile<32, 1, 1, 520, 520>(sF, sW, wm * 16, wn * 16, lane, acc);
        const int g = lane >> 2, tg = lane & 3;
        const int rA = wm * 16 + g, rB = wm * 16 + 8 + g;
#pragma unroll
        for (int nt = 0; nt < 2; ++nt) {
            const int cc = wn * 16 + nt * 8 + tg * 2;
            const float2 b = __ldg((const float2*)(fw_out_b + cc));
            const float2 r0 = *(const float2*)(g_h1 + (size_t)(node0 + rA) * 128 + cc);
            const float2 r1 = *(const float2*)(g_h1 + (size_t)(node0 + rB) * 128 + cc);
            sX[rA * 132 + cc]     = acc[0][nt][0] + b.x + r0.x;
            sX[rA * 132 + cc + 1] = acc[0][nt][1] + b.y + r0.y;
            sX[rB * 132 + cc]     = acc[0][nt][2] + b.x + r1.x;
            sX[rB * 132 + cc + 1] = acc[0][nt][3] + b.y + r1.y;
        }
    }
    __syncthreads();

    // LN2 + mask_v + store: warp w handles rows 2w, 2w+1 (32 rows total)
#pragma unroll
    for (int rr = 0; rr < 2; ++rr) {
        const int r = wid * 2 + rr;
        float x[4], sum = 0.f;
#pragma unroll
        for (int j = 0; j < 4; ++j) { x[j] = sX[r * 132 + lane + 32 * j]; sum += x[j]; }
#pragma unroll
        for (int o = 16; o >= 1; o >>= 1) sum += __shfl_xor_sync(0xffffffffu, sum, o);
        float mu = sum * (1.0f / 128.0f);
        float vs = 0.f;
#pragma unroll
        for (int j = 0; j < 4; ++j) { float d = x[j] - mu; vs += d * d; }
#pragma unroll
        for (int o = 16; o >= 1; o >>= 1) vs += __shfl_xor_sync(0xffffffffu, vs, o);
        float rs = rsqrtf(vs * (1.0f / 128.0f) + 1e-5f);
        float mv = mask_v[node0 + r];
#pragma unroll
        for (int j = 0; j < 4; ++j) {
            int c = lane + 32 * j;
            out[(size_t)(node0 + r) * 128 + c] =
                ((x[j] - mu) * rs * __ldg(ln2_g + c) + __ldg(ln2_b + c)) * mv;
        }
    }
}

// -------- launcher --------
extern "C" void kernel_launch(void* const* d_in, const int* in_sizes, int n_in,
                              void* d_out, int out_size) {
    const float* h_v         = (const float*)d_in[0];
    const float* h_e         = (const float*)d_in[1];
    const float* mask_v      = (const float*)d_in[2];
    const float* mask_attend = (const float*)d_in[3];
    const float* w1_w        = (const float*)d_in[4];
    const float* w1_b        = (const float*)d_in[5];
    const float* w2_b        = (const float*)d_in[7];
    const float* w3_b        = (const float*)d_in[9];
    const float* ln1_g       = (const float*)d_in[10];
    const float* ln1_b       = (const float*)d_in[11];
    const float* ln2_g       = (const float*)d_in[12];
    const float* ln2_b       = (const float*)d_in[13];
    const float* fw_in_b     = (const float*)d_in[15];
    const float* fw_out_b    = (const float*)d_in[17];
    float* out = (float*)d_out;

    static bool attr_done = false;
    if (!attr_done) {
        cudaFuncSetAttribute(k1_msg, cudaFuncAttributeMaxDynamicSharedMemorySize, K1_SMEM);
        cudaFuncSetAttribute(k2_ffn, cudaFuncAttributeMaxDynamicSharedMemorySize, K2_SMEM);
        attr_done = true;
    }

    prep_weights<<<896, 256>>>(w1_w, (const float*)d_in[6],
                               (const float*)d_in[8], (const float*)d_in[14],
                               (const float*)d_in[16]);
    prep_hv<<<NNODES / 16, 256>>>(h_v, w1_w);
    k1_msg<<<NNODES / 4, 256, K1_SMEM>>>(h_v, h_e, mask_attend,
                                         w1_b, w2_b, w3_b, ln1_g, ln1_b);
    k2_ffn<<<NNODES / 32, 512, K2_SMEM>>>(mask_v, fw_in_b, fw_out_b,
                                          ln2_g, ln2_b, out);
}

// round 17
// speedup vs baseline: 1.6463x; 1.0035x over previous
#include <cuda_runtime.h>
#include <cuda_fp16.h>
#include <cstdint>

#define DEVFN __device__ __forceinline__

#define NNODES 8192
#define HDIM   128
#define CIN    384
#define KTOT   512
#define FFD    512

// -------- persistent scratch --------
__device__ __half g_w1T[HDIM * KTOT];
__device__ __half g_w2T[HDIM * HDIM];
__device__ __half g_w3T[HDIM * HDIM];
__device__ __half g_fwInT[FFD * HDIM];
__device__ __half g_fwOutT[HDIM * FFD];
__device__ float  g_h1[NNODES * HDIM];
__device__ float  g_u[NNODES * HDIM];    // h_v @ w1[0:128] per node (f32)

// -------- helpers --------
DEVFN uint32_t smaddr(const void* p) { return (uint32_t)__cvta_generic_to_shared(p); }

DEVFN void ldmx4(uint32_t addr, uint32_t& r0, uint32_t& r1, uint32_t& r2, uint32_t& r3) {
    asm volatile("ldmatrix.sync.aligned.m8n8.x4.shared.b16 {%0,%1,%2,%3}, [%4];\n"
                 : "=r"(r0), "=r"(r1), "=r"(r2), "=r"(r3) : "r"(addr));
}

DEVFN void mma16816(float (&c)[4], const uint32_t (&a)[4], uint32_t b0, uint32_t b1) {
    asm volatile(
        "mma.sync.aligned.m16n8k16.row.col.f32.f16.f16.f32 "
        "{%0,%1,%2,%3}, {%4,%5,%6,%7}, {%8,%9}, {%0,%1,%2,%3};\n"
        : "+f"(c[0]), "+f"(c[1]), "+f"(c[2]), "+f"(c[3])
        : "r"(a[0]), "r"(a[1]), "r"(a[2]), "r"(a[3]), "r"(b0), "r"(b1));
}

DEVFN float gelu_f(float x) { return 0.5f * x * (1.0f + erff(x * 0.70710678118654752f)); }

// fp16 warp-tile GEMM (A/B k-contiguous, strides in halves)
template <int KSTEPS, int MTILES, int PT, int AST, int BST>
DEVFN void gemm_tile(const __half* sAp, const __half* sBp, int rowBase, int colBase,
                     int lane, float (&acc)[MTILES][2 * PT][4]) {
    const int lr = lane & 15;
    const int lc = (lane >> 4) * 8;
#pragma unroll
    for (int ks = 0; ks < KSTEPS; ++ks) {
        const int kk = ks * 16 + lc;
        uint32_t a[MTILES][4];
#pragma unroll
        for (int mt = 0; mt < MTILES; ++mt)
            ldmx4(smaddr(sAp + (size_t)(rowBase + mt * 16 + lr) * AST + kk),
                  a[mt][0], a[mt][1], a[mt][2], a[mt][3]);
#pragma unroll
        for (int p = 0; p < PT; ++p) {
            uint32_t b0, b1, b2, b3;
            ldmx4(smaddr(sBp + (size_t)(colBase + p * 16 + lr) * BST + kk), b0, b1, b2, b3);
#pragma unroll
            for (int mt = 0; mt < MTILES; ++mt) {
                mma16816(acc[mt][2 * p],     a[mt], b0, b2);
                mma16816(acc[mt][2 * p + 1], a[mt], b1, b3);
            }
        }
    }
}

template <int MTILES, int NT, int DST>
DEVFN void epi_gelu_store(float (&acc)[MTILES][NT][4], const float* __restrict__ bias,
                          __half* dst, int rowBase, int colBase, int lane) {
    const int g = lane >> 2, tg = lane & 3;
#pragma unroll
    for (int mt = 0; mt < MTILES; ++mt) {
        const int r0 = rowBase + mt * 16 + g;
#pragma unroll
        for (int nt = 0; nt < NT; ++nt) {
            const int cc = colBase + nt * 8 + tg * 2;
            const float2 b = __ldg((const float2*)(bias + cc));
            float v0 = gelu_f(acc[mt][nt][0] + b.x);
            float v1 = gelu_f(acc[mt][nt][1] + b.y);
            float v2 = gelu_f(acc[mt][nt][2] + b.x);
            float v3 = gelu_f(acc[mt][nt][3] + b.y);
            *(__half2*)(dst + (size_t)r0 * DST + cc)       = __floats2half2_rn(v0, v1);
            *(__half2*)(dst + (size_t)(r0 + 8) * DST + cc) = __floats2half2_rn(v2, v3);
        }
    }
}

// -------- kernel 0a: weight transpose/convert to fp16 --------
__global__ void prep_weights(const float* __restrict__ w1, const float* __restrict__ w2,
                             const float* __restrict__ w3, const float* __restrict__ fwin,
                             const float* __restrict__ fwout) {
    int i = blockIdx.x * 256 + threadIdx.x;
    if (i < 65536) {
        int h = i >> 9, k = i & 511;
        float v = (k < 384) ? w1[(128 + k) * 128 + h] : w1[(k - 384) * 128 + h];
        g_w1T[i] = __float2half(v);
    } else if (i < 81920) {
        int j = i - 65536; int h = j >> 7, k = j & 127;
        g_w2T[j] = __float2half(w2[k * 128 + h]);
    } else if (i < 98304) {
        int j = i - 81920; int h = j >> 7, k = j & 127;
        g_w3T[j] = __float2half(w3[k * 128 + h]);
    } else if (i < 163840) {
        int j = i - 98304; int f = j >> 7, k = j & 127;
        g_fwInT[j] = __float2half(fwin[k * 512 + f]);
    } else if (i < 229376) {
        int j = i - 163840; int h = j >> 9, k = j & 511;
        g_fwOutT[j] = __float2half(fwout[k * 128 + h]);
    }
}

// -------- kernel 0b: u[n] = h_v[n] @ w1[0:128] (exact f32) --------
__global__ void __launch_bounds__(256) prep_hv(const float* __restrict__ h_v,
                                               const float* __restrict__ w1) {
    __shared__ float sW[32 * 128];
    __shared__ float sV[16 * 32];
    const int tid = threadIdx.x;
    const int h = tid & 127, g = tid >> 7;
    const int node0 = blockIdx.x * 16;
    float acc[8];
#pragma unroll
    for (int i = 0; i < 8; ++i) acc[i] = 0.f;
    for (int kc = 0; kc < 4; ++kc) {
        for (int i = tid; i < 4096; i += 256) {
            int k = i >> 7, c = i & 127;
            sW[k * 128 + c] = w1[(kc * 32 + k) * 128 + c];
        }
        for (int i = tid; i < 512; i += 256) {
            int n = i >> 5, k = i & 31;
            sV[n * 32 + k] = h_v[(size_t)(node0 + n) * 128 + kc * 32 + k];
        }
        __syncthreads();
#pragma unroll 8
        for (int k = 0; k < 32; ++k) {
            float w = sW[k * 128 + h];
#pragma unroll
            for (int i = 0; i < 8; ++i) acc[i] += sV[(g * 8 + i) * 32 + k] * w;
        }
        __syncthreads();
    }
#pragma unroll
    for (int i = 0; i < 8; ++i)
        g_u[(size_t)(node0 + g * 8 + i) * 128 + h] = acc[i];
}

// -------- kernel 1: message MLP + mask + K-sum + residual + LN1 (proven) --------
#define K1_SMEM 93952
__global__ void __launch_bounds__(256, 2) k1_msg(
    const float* __restrict__ h_v, const float* __restrict__ h_e,
    const float* __restrict__ mask_attend,
    const float* __restrict__ w1_b, const float* __restrict__ w2_b,
    const float* __restrict__ w3_b,
    const float* __restrict__ ln1_g, const float* __restrict__ ln1_b) {
    extern __shared__ char smem[];
    __half* sA    = (__half*)smem;
    __half* sM    = (__half*)smem;
    __half* sB    = (__half*)(smem + 52224);
    float*  sHv   = (float*)(smem + 87040);
    float*  sMask = (float*)(smem + 89088);
    float*  sDh   = (float*)(smem + 89856);
    float*  sU    = (float*)(smem + 91904);

    const int tid = threadIdx.x, lane = tid & 31, wid = tid >> 5;
    const int wm = wid & 3, wn = wid >> 2;
    const int rowBase = wm * 48, colBase = wn * 64;
    const size_t tileRow = (size_t)blockIdx.x * 192;
    const int nodeBase = blockIdx.x * 4;

    for (int i = tid; i < 512; i += 256) {
        sHv[i] = h_v[(size_t)nodeBase * 128 + i];
        sU[i]  = g_u[(size_t)nodeBase * 128 + i];
    }
    for (int i = tid; i < 192; i += 256) sMask[i] = mask_attend[tileRow + i];
    __syncthreads();

    float acc[3][8][4];
#pragma unroll
    for (int a = 0; a < 3; a++)
#pragma unroll
        for (int b = 0; b < 8; b++)
#pragma unroll
            for (int c = 0; c < 4; c++) acc[a][b][c] = 0.f;

    const float4* heBase = (const float4*)(h_e + tileRow * CIN);
    for (int kc = 0; kc < 3; ++kc) {
#pragma unroll
        for (int i = 0; i < 24; ++i) {
            int idx = tid + i * 256;
            int r = idx >> 5, c4 = idx & 31;
            float4 v = __ldcs(heBase + (size_t)r * 96 + kc * 32 + c4);
            __half2* p = (__half2*)(sA + r * 136 + c4 * 4);
            p[0] = __floats2half2_rn(v.x, v.y);
            p[1] = __floats2half2_rn(v.z, v.w);
        }
#pragma unroll
        for (int i = 0; i < 8; ++i) {
            int idx = tid + i * 256;
            int n = idx >> 4, j = idx & 15;
            *(uint4*)(sB + n * 136 + j * 8) =
                *(const uint4*)(g_w1T + n * 512 + kc * 128 + j * 8);
        }
        __syncthreads();
        gemm_tile<8, 3, 4, 136, 136>(sA, sB, rowBase, colBase, lane, acc);
        __syncthreads();
    }

    // epilogue 1: + b1 + u[node], gelu -> sM; stage w2T -> sB
    {
        const int g = lane >> 2, tg = lane & 3;
        const float* uRow = sU + wm * 128;
#pragma unroll
        for (int mt = 0; mt < 3; ++mt) {
            const int r0 = rowBase + mt * 16 + g;
#pragma unroll
            for (int nt = 0; nt < 8; ++nt) {
                const int cc = colBase + nt * 8 + tg * 2;
                const float2 b = __ldg((const float2*)(w1_b + cc));
                const float2 u = *(const float2*)(uRow + cc);
                float v0 = gelu_f(acc[mt][nt][0] + b.x + u.x);
                float v1 = gelu_f(acc[mt][nt][1] + b.y + u.y);
                float v2 = gelu_f(acc[mt][nt][2] + b.x + u.x);
                float v3 = gelu_f(acc[mt][nt][3] + b.y + u.y);
                *(__half2*)(sM + (size_t)r0 * 136 + cc)       = __floats2half2_rn(v0, v1);
                *(__half2*)(sM + (size_t)(r0 + 8) * 136 + cc) = __floats2half2_rn(v2, v3);
            }
        }
    }
#pragma unroll
    for (int i = 0; i < 8; ++i) {
        int idx = tid + i * 256;
        int n = idx >> 4, j = idx & 15;
        *(uint4*)(sB + n * 136 + j * 8) = *(const uint4*)(g_w2T + n * 128 + j * 8);
    }
    __syncthreads();

#pragma unroll
    for (int a = 0; a < 3; a++)
#pragma unroll
        for (int b = 0; b < 8; b++)
#pragma unroll
            for (int c = 0; c < 4; c++) acc[a][b][c] = 0.f;
    gemm_tile<8, 3, 4, 136, 136>(sM, sB, rowBase, colBase, lane, acc);
    __syncthreads();

    epi_gelu_store<3, 8, 136>(acc, w2_b, sM, rowBase, colBase, lane);
#pragma unroll
    for (int i = 0; i < 8; ++i) {
        int idx = tid + i * 256;
        int n = idx >> 4, j = idx & 15;
        *(uint4*)(sB + n * 136 + j * 8) = *(const uint4*)(g_w3T + n * 128 + j * 8);
    }
    __syncthreads();

#pragma unroll
    for (int a = 0; a < 3; a++)
#pragma unroll
        for (int b = 0; b < 8; b++)
#pragma unroll
            for (int c = 0; c < 4; c++) acc[a][b][c] = 0.f;
    gemm_tile<8, 3, 4, 136, 136>(sM, sB, rowBase, colBase, lane, acc);

    {
        const int g = lane >> 2, tg = lane & 3;
        float mk0[3], mk1[3];
#pragma unroll
        for (int mt = 0; mt < 3; ++mt) {
            mk0[mt] = sMask[rowBase + mt * 16 + g];
            mk1[mt] = sMask[rowBase + mt * 16 + 8 + g];
        }
#pragma unroll
        for (int nt = 0; nt < 8; ++nt) {
            const int cc = colBase + nt * 8 + tg * 2;
            const float2 b3 = __ldg((const float2*)(w3_b + cc));
            float s0 = 0.f, s1 = 0.f;
#pragma unroll
            for (int mt = 0; mt < 3; ++mt) {
                s0 += (acc[mt][nt][0] + b3.x) * mk0[mt] + (acc[mt][nt][2] + b3.x) * mk1[mt];
                s1 += (acc[mt][nt][1] + b3.y) * mk0[mt] + (acc[mt][nt][3] + b3.y) * mk1[mt];
            }
#pragma unroll
            for (int o = 4; o <= 16; o <<= 1) {
                s0 += __shfl_xor_sync(0xffffffffu, s0, o);
                s1 += __shfl_xor_sync(0xffffffffu, s1, o);
            }
            if (g == 0) *(float2*)(sDh + wm * 128 + cc) = make_float2(s0, s1);
        }
    }
    __syncthreads();

    if (wid < 4) {
        const int node = wid;
        float x[4], sum = 0.f;
#pragma unroll
        for (int j = 0; j < 4; ++j) {
            int c = lane + 32 * j;
            x[j] = sHv[node * 128 + c] + sDh[node * 128 + c] * (1.0f / 30.0f);
            sum += x[j];
        }
#pragma unroll
        for (int o = 16; o >= 1; o >>= 1) sum += __shfl_xor_sync(0xffffffffu, sum, o);
        float mu = sum * (1.0f / 128.0f);
        float vs = 0.f;
#pragma unroll
        for (int j = 0; j < 4; ++j) { float d = x[j] - mu; vs += d * d; }
#pragma unroll
        for (int o = 16; o >= 1; o >>= 1) vs += __shfl_xor_sync(0xffffffffu, vs, o);
        float rs = rsqrtf(vs * (1.0f / 128.0f) + 1e-5f);
#pragma unroll
        for (int j = 0; j < 4; ++j) {
            int c = lane + 32 * j;
            g_h1[(size_t)(nodeBase + node) * 128 + c] =
                (x[j] - mu) * rs * __ldg(ln1_g + c) + __ldg(ln1_b + c);
        }
    }
}

// -------- kernel 2: FFN + residual + LN2 + mask_v --------
// REWORK: 16 nodes/CTA, 256 threads, chunked weight staging for 2 CTAs/SM.
// smem: sW @0 (max(256x136, 128x264) f16 = 69632), sF @69632 ([16][520] f16, 16640),
//       sH @86272 ([16][136] f16, 4352) aliased by sX ([16][132] f32, 8448) -> 94720.
#define K2_SW 0
#define K2_SF 69632
#define K2_SH 86272
#define K2_SMEM 94720
__global__ void __launch_bounds__(256, 2) k2_ffn(
    const float* __restrict__ mask_v,
    const float* __restrict__ fw_in_b, const float* __restrict__ fw_out_b,
    const float* __restrict__ ln2_g, const float* __restrict__ ln2_b,
    float* __restrict__ out) {
    extern __shared__ char smem[];
    __half* sW = (__half*)(smem + K2_SW);
    __half* sF = (__half*)(smem + K2_SF);
    __half* sH = (__half*)(smem + K2_SH);
    float*  sX = (float*)(smem + K2_SH);   // aliases sH (dead after GEMM-in)

    const int tid = threadIdx.x, lane = tid & 31, wid = tid >> 5;
    const int node0 = blockIdx.x * 16;

    for (int i = tid; i < 2048; i += 256) {
        int r = i >> 7, c = i & 127;
        sH[r * 136 + c] = __float2half(g_h1[(size_t)(node0 + r) * 128 + c]);
    }

    // ---- GEMM-in: [16 x 128] x [128 -> 512], FF staged in 2 chunks of 256 ----
    for (int fc = 0; fc < 2; ++fc) {
        for (int i = tid; i < 4096; i += 256) {          // 256 rows x 16 chunks of 16B
            int n = i >> 4, j = i & 15;
            *(uint4*)(sW + n * 136 + j * 8) =
                *(const uint4*)(g_fwInT + (fc * 256 + n) * 128 + j * 8);
        }
        __syncthreads();
        float acc[1][4][4];
#pragma unroll
        for (int b = 0; b < 4; b++)
#pragma unroll
            for (int c = 0; c < 4; c++) acc[0][b][c] = 0.f;
        // warp covers rows 0..15, local FF cols wid*32..+31 (PT=2)
        gemm_tile<8, 1, 2, 136, 136>(sH, sW, 0, wid * 32, lane, acc);
        // epilogue: global FF col = fc*256 + local
        {
            const int g = lane >> 2, tg = lane & 3;
            const int r0 = g;
#pragma unroll
            for (int nt = 0; nt < 4; ++nt) {
                const int cc = fc * 256 + wid * 32 + nt * 8 + tg * 2;
                const float2 b = __ldg((const float2*)(fw_in_b + cc));
                float v0 = gelu_f(acc[0][nt][0] + b.x);
                float v1 = gelu_f(acc[0][nt][1] + b.y);
                float v2 = gelu_f(acc[0][nt][2] + b.x);
                float v3 = gelu_f(acc[0][nt][3] + b.y);
                *(__half2*)(sF + (size_t)r0 * 520 + cc)       = __floats2half2_rn(v0, v1);
                *(__half2*)(sF + (size_t)(r0 + 8) * 520 + cc) = __floats2half2_rn(v2, v3);
            }
        }
        __syncthreads();   // sW reads done; safe to restage
    }

    // ---- GEMM-out: [16 x 512] x [512 -> 128], K staged in 2 chunks of 256 ----
    float acc[1][2][4];
#pragma unroll
    for (int b = 0; b < 2; b++)
#pragma unroll
        for (int c = 0; c < 4; c++) acc[0][b][c] = 0.f;
    for (int kc = 0; kc < 2; ++kc) {
        for (int i = tid; i < 4096; i += 256) {          // 128 rows x 32 chunks of 16B
            int n = i >> 5, j = i & 31;
            *(uint4*)(sW + n * 264 + j * 8) =
                *(const uint4*)(g_fwOutT + n * 512 + kc * 256 + j * 8);
        }
        __syncthreads();
        // warp covers rows 0..15, H cols wid*16..+15 (PT=1), K-chunk via sF offset
        gemm_tile<16, 1, 1, 520, 264>(sF + kc * 256, sW, 0, wid * 16, lane, acc);
        __syncthreads();
    }

    // epilogue: + bias + residual -> sX (aliases dead sH)
    {
        const int g = lane >> 2, tg = lane & 3;
#pragma unroll
        for (int nt = 0; nt < 2; ++nt) {
            const int cc = wid * 16 + nt * 8 + tg * 2;
            const float2 b = __ldg((const float2*)(fw_out_b + cc));
            const float2 r0 = *(const float2*)(g_h1 + (size_t)(node0 + g) * 128 + cc);
            const float2 r1 = *(const float2*)(g_h1 + (size_t)(node0 + 8 + g) * 128 + cc);
            sX[g * 132 + cc]           = acc[0][nt][0] + b.x + r0.x;
            sX[g * 132 + cc + 1]       = acc[0][nt][1] + b.y + r0.y;
            sX[(g + 8) * 132 + cc]     = acc[0][nt][2] + b.x + r1.x;
            sX[(g + 8) * 132 + cc + 1] = acc[0][nt][3] + b.y + r1.y;
        }
    }
    __syncthreads();

    // LN2 + mask_v + store: warp w handles rows 2w, 2w+1
#pragma unroll
    for (int rr = 0; rr < 2; ++rr) {
        const int r = wid * 2 + rr;
        float x[4], sum = 0.f;
#pragma unroll
        for (int j = 0; j < 4; ++j) { x[j] = sX[r * 132 + lane + 32 * j]; sum += x[j]; }
#pragma unroll
        for (int o = 16; o >= 1; o >>= 1) sum += __shfl_xor_sync(0xffffffffu, sum, o);
        float mu = sum * (1.0f / 128.0f);
        float vs = 0.f;
#pragma unroll
        for (int j = 0; j < 4; ++j) { float d = x[j] - mu; vs += d * d; }
#pragma unroll
        for (int o = 16; o >= 1; o >>= 1) vs += __shfl_xor_sync(0xffffffffu, vs, o);
        float rs = rsqrtf(vs * (1.0f / 128.0f) + 1e-5f);
        float mv = mask_v[node0 + r];
#pragma unroll
        for (int j = 0; j < 4; ++j) {
            int c = lane + 32 * j;
            out[(size_t)(node0 + r) * 128 + c] =
                ((x[j] - mu) * rs * __ldg(ln2_g + c) + __ldg(ln2_b + c)) * mv;
        }
    }
}

// -------- launcher --------
extern "C" void kernel_launch(void* const* d_in, const int* in_sizes, int n_in,
                              void* d_out, int out_size) {
    const float* h_v         = (const float*)d_in[0];
    const float* h_e         = (const float*)d_in[1];
    const float* mask_v      = (const float*)d_in[2];
    const float* mask_attend = (const float*)d_in[3];
    const float* w1_w        = (const float*)d_in[4];
    const float* w1_b        = (const float*)d_in[5];
    const float* w2_b        = (const float*)d_in[7];
    const float* w3_b        = (const float*)d_in[9];
    const float* ln1_g       = (const float*)d_in[10];
    const float* ln1_b       = (const float*)d_in[11];
    const float* ln2_g       = (const float*)d_in[12];
    const float* ln2_b       = (const float*)d_in[13];
    const float* fw_in_b     = (const float*)d_in[15];
    const float* fw_out_b    = (const float*)d_in[17];
    float* out = (float*)d_out;

    static bool attr_done = false;
    if (!attr_done) {
        cudaFuncSetAttribute(k1_msg, cudaFuncAttributeMaxDynamicSharedMemorySize, K1_SMEM);
        cudaFuncSetAttribute(k2_ffn, cudaFuncAttributeMaxDynamicSharedMemorySize, K2_SMEM);
        attr_done = true;
    }

    prep_weights<<<896, 256>>>(w1_w, (const float*)d_in[6],
                               (const float*)d_in[8], (const float*)d_in[14],
                               (const float*)d_in[16]);
    prep_hv<<<NNODES / 16, 256>>>(h_v, w1_w);
    k1_msg<<<NNODES / 4, 256, K1_SMEM>>>(h_v, h_e, mask_attend,
                                         w1_b, w2_b, w3_b, ln1_g, ln1_b);
    k2_ffn<<<NNODES / 16, 256, K2_SMEM>>>(mask_v, fw_in_b, fw_out_b,
                                          ln2_g, ln2_b, out);
}